// round 13
// baseline (speedup 1.0000x reference)
#include <cuda_runtime.h>
#include <cuda_fp16.h>
#include <float.h>
#include <math.h>

#define DMAX 64
#define NMAX 100000
#define EMAX 1600000
#define GMAX 512
#define LMAX 3
#define HS_STRIDE 68
#define SGRID 148
#define STHREADS 1024
#define FGRID 391

// ---------------- scratch (no allocations allowed) ----------------
__device__ __align__(16) __half2 g_hws2[NMAX * 32];  // fp16 scaled conv output
__device__ __align__(16) __half2 g_pre2[NMAX * 32];  // fp16 pre-BN aggregates
__device__ float g_h[NMAX * DMAX];
__device__ float g_dinv[NMAX];
__device__ float g_Wpack[LMAX * 4096];               // tf32 W fragments
__device__ int   g_cnt[NMAX];
__device__ int   g_incl[NMAX];
__device__ int   g_rowptr[NMAX + 1];
__device__ int   g_wpos[NMAX];
__device__ int   g_srcs[EMAX];
__device__ int   g_part[128];
__device__ float g_bnsum[LMAX * DMAX], g_bnsumsq[LMAX * DMAX];
__device__ int   g_gcnt[GMAX];
__device__ int   g_goff[GMAX];
__device__ unsigned g_barrier;   // monotonic across uses AND graph replays

// ---------------- helpers ----------------
__device__ __forceinline__ float gelu_exact(float x) {
    return 0.5f * x * (1.0f + erff(x * 0.70710678118654752f));
}

__device__ __forceinline__ unsigned tf32cvt(float f) {
    unsigned r;
    asm("cvt.rna.tf32.f32 %0, %1;" : "=r"(r) : "f"(f));
    return r;
}

__device__ __forceinline__ void mma_tf32(float& c0, float& c1, float& c2, float& c3,
                                         unsigned a0, unsigned a1, unsigned a2,
                                         unsigned a3, unsigned b0, unsigned b1) {
    asm("mma.sync.aligned.m16n8k8.row.col.f32.tf32.tf32.f32 "
        "{%0,%1,%2,%3},{%4,%5,%6,%7},{%8,%9},{%0,%1,%2,%3};"
        : "+f"(c0), "+f"(c1), "+f"(c2), "+f"(c3)
        : "r"(a0), "r"(a1), "r"(a2), "r"(a3), "r"(b0), "r"(b1));
}

__device__ __forceinline__ void acc8(uint4 v, float* a) {
    float2 f;
    f = __half22float2(*(__half2*)&v.x); a[0] += f.x; a[1] += f.y;
    f = __half22float2(*(__half2*)&v.y); a[2] += f.x; a[3] += f.y;
    f = __half22float2(*(__half2*)&v.z); a[4] += f.x; a[5] += f.y;
    f = __half22float2(*(__half2*)&v.w); a[6] += f.x; a[7] += f.y;
}

__device__ __forceinline__ float wsum(float v) {
#pragma unroll
    for (int o = 16; o; o >>= 1) v += __shfl_xor_sync(0xffffffffu, v, o);
    return v;
}

// Monotonic-ticket grid barrier (148 blocks, guaranteed co-resident).
__device__ __forceinline__ void grid_bar() {
    __syncthreads();
    if (threadIdx.x == 0) {
        unsigned ticket;
        asm volatile("atom.add.release.gpu.u32 %0, [%1], %2;"
                     : "=r"(ticket) : "l"(&g_barrier), "r"(1u) : "memory");
        ticket += 1;
        unsigned goal = ((ticket - 1) / SGRID + 1) * SGRID;
        unsigned cur;
        do {
            asm volatile("ld.acquire.gpu.u32 %0, [%1];"
                         : "=r"(cur) : "l"(&g_barrier) : "memory");
        } while (cur < goal);
    }
    __syncthreads();
}

// ---------------- persistent setup: zero+hist+scan+place+Wpack ----------------
__global__ __launch_bounds__(STHREADS, 1) void setup_persist(
    const int* __restrict__ ei, const int* __restrict__ batch,
    const float* __restrict__ convW, int E, int n) {
    __shared__ int sh[STHREADS];
    const int t = threadIdx.x;
    const int b = blockIdx.x;
    const int gsz = SGRID * STHREADS;
    const int gtid = b * STHREADS + t;

    // phase 0: zero accumulators + pack tf32 W fragments
    for (int i = gtid; i < n; i += gsz) g_cnt[i] = 0;
    if (gtid < GMAX) g_gcnt[gtid] = 0;
    if (gtid < LMAX * DMAX) { g_bnsum[gtid] = 0.f; g_bnsumsq[gtid] = 0.f; }
    for (int idx = gtid; idx < LMAX * 2048; idx += gsz) {
        int L = idx >> 11, i = idx & 2047;
        int ks = i >> 8;
        int gsub = (i >> 5) & 7;
        int l = i & 31;
        int ltid = l & 3, lgid = l >> 2;
        const float* W = convW + L * 4096;
        unsigned b0 = tf32cvt(W[(ks * 8 + ltid) * 64 + gsub * 8 + lgid]);
        unsigned b1 = tf32cvt(W[(ks * 8 + ltid + 4) * 64 + gsub * 8 + lgid]);
        g_Wpack[L * 4096 + i * 2]     = __uint_as_float(b0);
        g_Wpack[L * 4096 + i * 2 + 1] = __uint_as_float(b1);
    }
    grid_bar();

    // phase 1: histograms
    for (int e = gtid; e < E; e += gsz) atomicAdd(&g_cnt[ei[E + e]], 1);
    for (int i = gtid; i < n; i += gsz) atomicAdd(&g_gcnt[batch[i]], 1);
    grid_bar();

    // phase 2: per-chunk inclusive scans (1024-wide)
    const int nchunk = (n + STHREADS - 1) / STHREADS;
    for (int c = b; c < nchunk; c += SGRID) {
        int i = c * STHREADS + t;
        int v = (i < n) ? g_cnt[i] : 0;
        sh[t] = v;
        __syncthreads();
        for (int o = 1; o < STHREADS; o <<= 1) {
            int u = (t >= o) ? sh[t - o] : 0;
            __syncthreads();
            sh[t] += u;
            __syncthreads();
        }
        if (i < n) g_incl[i] = sh[t];
        if (t == STHREADS - 1) g_part[c] = sh[STHREADS - 1];
        __syncthreads();
    }
    grid_bar();

    // phase 3: scan partials (block 0) + graph counts (block 1)
    if (b == 0) {
        if (t < 128) {
            int v = (t < nchunk) ? g_part[t] : 0;
            sh[t] = v;
            __syncthreads();
            for (int o = 1; o < 128; o <<= 1) {
                int u = (t >= o) ? sh[t - o] : 0;
                __syncthreads();
                sh[t] += u;
                __syncthreads();
            }
            g_part[t] = sh[t] - v;
        } else {
            for (int o = 1; o < 128; o <<= 1) { __syncthreads(); __syncthreads(); }
            __syncthreads();
        }
    } else if (b == 1) {
        if (t < GMAX) {
            int v = g_gcnt[t];
            sh[t] = v;
            __syncthreads();
            for (int o = 1; o < GMAX; o <<= 1) {
                int u = (t >= o) ? sh[t - o] : 0;
                __syncthreads();
                sh[t] += u;
                __syncthreads();
            }
            g_goff[t] = sh[t] - v;
        } else {
            for (int o = 1; o < GMAX; o <<= 1) { __syncthreads(); __syncthreads(); }
            __syncthreads();
        }
    }
    grid_bar();

    // phase 4: finish CSR rowptrs + dinv
    for (int i = gtid; i < n; i += gsz) {
        int c = g_cnt[i];
        int incl = g_incl[i] + g_part[i / STHREADS];
        int rp = incl - c;
        g_rowptr[i] = rp;
        g_wpos[i]   = rp;
        g_dinv[i]   = rsqrtf((float)(c + 1));
        if (i == n - 1) g_rowptr[n] = incl;
    }
    grid_bar();

    // phase 5: place edges
    for (int e = gtid; e < E; e += gsz) {
        int s = ei[e], d = ei[E + e];
        g_srcs[atomicAdd(&g_wpos[d], 1)] = s;
    }
}

// ---------------- fused layer: multi-tile [transform] + tf32 MMA GEMM ---------
// Grid = FGRID blocks; each loads Bf once and loops over ~4 tiles.
__global__ __launch_bounds__(256) void fused_layer(
    const float* __restrict__ xsrc,
    const __half2* __restrict__ pre2,
    const float* __restrict__ bnsum, const float* __restrict__ bnsumsq,
    const float* __restrict__ bng, const float* __restrict__ bnb,
    const float* __restrict__ lng, const float* __restrict__ lnb,
    float* __restrict__ hio, int useRes,
    const float* __restrict__ Wp, float invN, int n) {
    __shared__ float Bf[4096];                // prepacked B fragments
    __shared__ float Hs[64 * HS_STRIDE];      // tf32-converted H tile
    int t = threadIdx.x;
    int w = t >> 5, lane = t & 31;
    int gid = lane >> 2, tid = lane & 3;

    // coalesced copy of prepacked fragments (once per block)
    for (int i = t; i < 1024; i += 256)
        ((float4*)Bf)[i] = ((const float4*)Wp)[i];

    // per-thread transform constants (once per block)
    float sc0 = 0.f, sh0 = 0.f, sc1 = 0.f, sh1 = 0.f;
    float lg0 = 0.f, lb0 = 0.f, lg1 = 0.f, lb1 = 0.f;
    if (pre2 != nullptr) {
        int f0 = 2 * lane, f1 = f0 + 1;
        float mu0 = bnsum[f0] * invN;
        float var0 = bnsumsq[f0] * invN - mu0 * mu0;
        sc0 = rsqrtf(var0 + 1e-5f) * bng[f0];
        sh0 = bnb[f0] - mu0 * sc0;
        float mu1 = bnsum[f1] * invN;
        float var1 = bnsumsq[f1] * invN - mu1 * mu1;
        sc1 = rsqrtf(var1 + 1e-5f) * bng[f1];
        sh1 = bnb[f1] - mu1 * sc1;
        lg0 = lng[f0]; lb0 = lnb[f0];
        lg1 = lng[f1]; lb1 = lnb[f1];
    }

    const int ntiles = (n + 63) >> 6;
    const int m0 = (w & 3) * 16;
    const int n0 = (w >> 2) * 32;

    for (int tile = blockIdx.x; tile < ntiles; tile += FGRID) {
        int row0 = tile * 64;
        if (pre2 == nullptr) {
            for (int i = t; i < 1024; i += 256) {
                int r = i >> 4, q = i & 15;
                int row = row0 + r;
                float4 v = (row < n) ? __ldg(&((const float4*)xsrc)[row * 16 + q])
                                     : make_float4(0.f, 0.f, 0.f, 0.f);
                float* hp = &Hs[r * HS_STRIDE + q * 4];
                hp[0] = __uint_as_float(tf32cvt(v.x));
                hp[1] = __uint_as_float(tf32cvt(v.y));
                hp[2] = __uint_as_float(tf32cvt(v.z));
                hp[3] = __uint_as_float(tf32cvt(v.w));
            }
        } else {
            int f0 = 2 * lane, f1 = f0 + 1;
#pragma unroll
            for (int rr = 0; rr < 8; rr++) {
                int r = w * 8 + rr;
                int row = row0 + r;
                if (row < n) {
                    float2 pv = __half22float2(pre2[row * 32 + lane]);
                    float v0 = pv.x * sc0 + sh0;
                    float v1 = pv.y * sc1 + sh1;
                    if (useRes) {
                        float2 hv = ((const float2*)hio)[row * 32 + lane];
                        v0 += hv.x; v1 += hv.y;
                    }
                    float s = wsum(v0 + v1);
                    float mu = s * (1.0f / 64.0f);
                    float d0 = v0 - mu, d1 = v1 - mu;
                    float vv = wsum(d0 * d0 + d1 * d1);
                    float rstd = rsqrtf(vv * (1.0f / 64.0f) + 1e-5f);
                    float y0 = gelu_exact(d0 * rstd * lg0 + lb0);
                    float y1 = gelu_exact(d1 * rstd * lg1 + lb1);
                    Hs[r * HS_STRIDE + f0] = __uint_as_float(tf32cvt(y0));
                    Hs[r * HS_STRIDE + f1] = __uint_as_float(tf32cvt(y1));
                    float2 st; st.x = y0; st.y = y1;
                    ((float2*)hio)[row * 32 + lane] = st;
                } else {
                    Hs[r * HS_STRIDE + f0] = 0.f;
                    Hs[r * HS_STRIDE + f1] = 0.f;
                }
            }
        }
        __syncthreads();

        float c[4][4];
#pragma unroll
        for (int s = 0; s < 4; s++)
#pragma unroll
            for (int j = 0; j < 4; j++) c[s][j] = 0.f;

        const float* Ar0 = &Hs[(m0 + gid) * HS_STRIDE];
        const float* Ar1 = &Hs[(m0 + gid + 8) * HS_STRIDE];
#pragma unroll
        for (int ks = 0; ks < 8; ks++) {
            int k0 = ks * 8;
            unsigned a0 = __float_as_uint(Ar0[k0 + tid]);
            unsigned a1 = __float_as_uint(Ar1[k0 + tid]);
            unsigned a2 = __float_as_uint(Ar0[k0 + tid + 4]);
            unsigned a3 = __float_as_uint(Ar1[k0 + tid + 4]);
#pragma unroll
            for (int s = 0; s < 4; s++) {
                int gsub = (n0 >> 3) + s;
                float2 b = *(const float2*)&Bf[((ks * 8 + gsub) * 32 + lane) * 2];
                mma_tf32(c[s][0], c[s][1], c[s][2], c[s][3],
                         a0, a1, a2, a3,
                         __float_as_uint(b.x), __float_as_uint(b.y));
            }
        }

        int rowa = row0 + m0 + gid;
        int rowb = rowa + 8;
        float dia = (rowa < n) ? g_dinv[rowa] : 0.f;
        float dib = (rowb < n) ? g_dinv[rowb] : 0.f;
        __half2* hw = (__half2*)g_hws2;
#pragma unroll
        for (int s = 0; s < 4; s++) {
            int col = n0 + s * 8 + tid * 2;
            if (rowa < n)
                hw[rowa * 32 + (col >> 1)] = __floats2half2_rn(c[s][0] * dia, c[s][1] * dia);
            if (rowb < n)
                hw[rowb * 32 + (col >> 1)] = __floats2half2_rn(c[s][2] * dib, c[s][3] * dib);
        }
        __syncthreads();
    }
}

// ---- CSR aggregate: 4 rows/warp, 8 lanes x 16B per row, + BN partials --------
__global__ __launch_bounds__(512) void aggregate(const float* __restrict__ convB,
                                                 float* __restrict__ bnsum,
                                                 float* __restrict__ bnsumsq,
                                                 int n) {
    __shared__ float bs[64], bs2[64];
    int t = threadIdx.x;
    if (t < 64) { bs[t] = 0.f; bs2[t] = 0.f; }
    __syncthreads();
    int warp = (blockIdx.x * 512 + t) >> 5;
    int lane = t & 31;
    int sub = lane & 7;
    int group = lane >> 3;
    int r = warp * 4 + group;
    float a[8];
#pragma unroll
    for (int j = 0; j < 8; j++) a[j] = 0.f;
    float psum[8], psq[8];
    bool valid = (r < n);
    if (valid) {
        acc8(((const uint4*)g_hws2)[r * 8 + sub], a);
        int p0 = g_rowptr[r], p1 = g_rowptr[r + 1];
#pragma unroll 4
        for (int p = p0; p < p1; p++) {
            int s = g_srcs[p];
            acc8(((const uint4*)g_hws2)[s * 8 + sub], a);
        }
        float di = g_dinv[r];
#pragma unroll
        for (int j = 0; j < 8; j++) {
            float pv = fmaf(di, a[j], convB[sub * 8 + j]);
            a[j] = pv;
            psum[j] = pv;
            psq[j] = pv * pv;
        }
        __half2 h0 = __floats2half2_rn(a[0], a[1]);
        __half2 h1 = __floats2half2_rn(a[2], a[3]);
        __half2 h2 = __floats2half2_rn(a[4], a[5]);
        __half2 h3 = __floats2half2_rn(a[6], a[7]);
        uint4 st;
        st.x = *(unsigned*)&h0; st.y = *(unsigned*)&h1;
        st.z = *(unsigned*)&h2; st.w = *(unsigned*)&h3;
        ((uint4*)g_pre2)[r * 8 + sub] = st;
    } else {
#pragma unroll
        for (int j = 0; j < 8; j++) { psum[j] = 0.f; psq[j] = 0.f; }
    }
#pragma unroll
    for (int j = 0; j < 8; j++) {
        psum[j] += __shfl_xor_sync(0xffffffffu, psum[j], 8);
        psq[j]  += __shfl_xor_sync(0xffffffffu, psq[j], 8);
        psum[j] += __shfl_xor_sync(0xffffffffu, psum[j], 16);
        psq[j]  += __shfl_xor_sync(0xffffffffu, psq[j], 16);
    }
    if (group == 0) {
#pragma unroll
        for (int j = 0; j < 8; j++) {
            atomicAdd(&bs[sub * 8 + j], psum[j]);
            atomicAdd(&bs2[sub * 8 + j], psq[j]);
        }
    }
    __syncthreads();
    if (t < 64) {
        atomicAdd(&bnsum[t], bs[t]);
        atomicAdd(&bnsumsq[t], bs2[t]);
    }
}

// ---- fused: final BN+res+LN+GELU transform + pool + MLP head per graph -------
__global__ __launch_bounds__(256) void pool_mlp(
    const float* __restrict__ bnsum, const float* __restrict__ bnsumsq,
    const float* __restrict__ bng, const float* __restrict__ bnb,
    const float* __restrict__ lng, const float* __restrict__ lnb,
    const float* __restrict__ W1, const float* __restrict__ b1,
    const float* __restrict__ l1g, const float* __restrict__ l1b,
    const float* __restrict__ W2, const float* __restrict__ b2,
    const float* __restrict__ l2g, const float* __restrict__ l2b,
    const float* __restrict__ W3, const float* __restrict__ b3,
    float* __restrict__ out, float invN) {
    int g = blockIdx.x, t = threadIdx.x;
    __shared__ float zs[192];
    __shared__ float shs[8][64], shm[8][64];
    __shared__ float s2[128];
    __shared__ float red[128];

    int start = g_goff[g], cnt = g_gcnt[g];
    int w = t >> 5, lane = t & 31;
    int f0 = 2 * lane, f1 = f0 + 1;

    float mu0 = bnsum[f0] * invN;
    float var0 = bnsumsq[f0] * invN - mu0 * mu0;
    float sc0 = rsqrtf(var0 + 1e-5f) * bng[f0];
    float sh0 = bnb[f0] - mu0 * sc0;
    float mu1 = bnsum[f1] * invN;
    float var1 = bnsumsq[f1] * invN - mu1 * mu1;
    float sc1 = rsqrtf(var1 + 1e-5f) * bng[f1];
    float sh1 = bnb[f1] - mu1 * sc1;
    float lg0 = lng[f0], lb0 = lnb[f0];
    float lg1 = lng[f1], lb1 = lnb[f1];

    float s0 = 0.f, s1 = 0.f, m0 = -FLT_MAX, m1 = -FLT_MAX;
    for (int r = start + w; r < start + cnt; r += 8) {
        float2 pv = __half22float2(g_pre2[r * 32 + lane]);
        float2 hv = ((const float2*)g_h)[r * 32 + lane];
        float v0 = pv.x * sc0 + sh0 + hv.x;
        float v1 = pv.y * sc1 + sh1 + hv.y;
        float s = wsum(v0 + v1);
        float mu = s * (1.0f / 64.0f);
        float d0 = v0 - mu, d1 = v1 - mu;
        float vv = wsum(d0 * d0 + d1 * d1);
        float rstd = rsqrtf(vv * (1.0f / 64.0f) + 1e-5f);
        float y0 = gelu_exact(d0 * rstd * lg0 + lb0);
        float y1 = gelu_exact(d1 * rstd * lg1 + lb1);
        s0 += y0; s1 += y1;
        m0 = fmaxf(m0, y0); m1 = fmaxf(m1, y1);
    }
    shs[w][f0] = s0; shs[w][f1] = s1;
    shm[w][f0] = m0; shm[w][f1] = m1;
    __syncthreads();
    if (t < 64) {
        float s = 0.f, m = -FLT_MAX;
#pragma unroll
        for (int k = 0; k < 8; k++) {
            s += shs[k][t];
            m = fmaxf(m, shm[k][t]);
        }
        float mean = (cnt > 0) ? s / (float)cnt : 0.f;
        if (cnt == 0) { m = 0.f; s = 0.f; }
        zs[t] = mean;
        zs[64 + t] = m;
        zs[128 + t] = s;
    }
    __syncthreads();

    float accv = 0.f;
    if (t < 128) {
        accv = b1[t];
#pragma unroll 4
        for (int k = 0; k < 192; k++) accv = fmaf(zs[k], W1[k * 128 + t], accv);
        red[t] = accv;
    }
    __syncthreads();
    if (t < 128) {
        for (int o = 64; o > 0; o >>= 1) {
            if (t < o) red[t] += red[t + o];
            __syncwarp(0xffffffffu);
            if (o > 32) __syncthreads();
        }
    }
    __syncthreads();
    float mu = red[0] * (1.0f / 128.0f);
    __syncthreads();
    float dv = accv - mu;
    if (t < 128) red[t] = dv * dv;
    __syncthreads();
    if (t < 128) {
        for (int o = 64; o > 0; o >>= 1) {
            if (t < o) red[t] += red[t + o];
            __syncwarp(0xffffffffu);
            if (o > 32) __syncthreads();
        }
    }
    __syncthreads();
    float rstd = rsqrtf(red[0] * (1.0f / 128.0f) + 1e-5f);
    __syncthreads();
    if (t < 128) s2[t] = gelu_exact(dv * rstd * l1g[t] + l1b[t]);
    __syncthreads();
    float acc2 = 0.f;
    if (t < 64) {
        acc2 = b2[t];
#pragma unroll 4
        for (int k = 0; k < 128; k++) acc2 = fmaf(s2[k], W2[k * 64 + t], acc2);
    }
    if (t < 128) red[t] = (t < 64) ? acc2 : 0.f;
    __syncthreads();
    if (t < 128) {
        for (int o = 64; o > 0; o >>= 1) {
            if (t < o) red[t] += red[t + o];
            __syncwarp(0xffffffffu);
            if (o > 32) __syncthreads();
        }
    }
    __syncthreads();
    float mu2 = red[0] * (1.0f / 64.0f);
    __syncthreads();
    float dv2 = acc2 - mu2;
    if (t < 128) red[t] = (t < 64) ? dv2 * dv2 : 0.f;
    __syncthreads();
    if (t < 128) {
        for (int o = 64; o > 0; o >>= 1) {
            if (t < o) red[t] += red[t + o];
            __syncwarp(0xffffffffu);
            if (o > 32) __syncthreads();
        }
    }
    __syncthreads();
    float rstd2 = rsqrtf(red[0] * (1.0f / 64.0f) + 1e-5f);
    __syncthreads();
    float y2 = 0.f;
    if (t < 64) y2 = gelu_exact(dv2 * rstd2 * l2g[t] + l2b[t]);
    if (t < 128) red[t] = (t < 64) ? y2 * W3[t] : 0.f;
    __syncthreads();
    if (t < 128) {
        for (int o = 64; o > 0; o >>= 1) {
            if (t < o) red[t] += red[t + o];
            __syncwarp(0xffffffffu);
            if (o > 32) __syncthreads();
        }
    }
    __syncthreads();
    if (t == 0) out[g] = red[0] + b3[0];
}

// ---------------- host ----------------
extern "C" void kernel_launch(void* const* d_in, const int* in_sizes, int n_in,
                              void* d_out, int out_size) {
    const float* x     = (const float*)d_in[0];
    const int*   ei    = (const int*)d_in[1];
    const int*   batch = (const int*)d_in[2];
    const float* convW = (const float*)d_in[3];
    const float* convB = (const float*)d_in[4];
    const float* bn_g  = (const float*)d_in[5];
    const float* bn_b  = (const float*)d_in[6];
    const float* ln_g  = (const float*)d_in[7];
    const float* ln_b  = (const float*)d_in[8];
    const float* W1    = (const float*)d_in[9];
    const float* b1    = (const float*)d_in[10];
    const float* l1g   = (const float*)d_in[11];
    const float* l1b   = (const float*)d_in[12];
    const float* W2    = (const float*)d_in[13];
    const float* b2    = (const float*)d_in[14];
    const float* l2g   = (const float*)d_in[15];
    const float* l2b   = (const float*)d_in[16];
    const float* W3    = (const float*)d_in[17];
    const float* b3    = (const float*)d_in[18];
    float* out = (float*)d_out;

    const int N = in_sizes[0] / 64;
    const int E = in_sizes[1] / 2;
    const int G = out_size;
    const float invN = 1.0f / (float)N;

    float* p_h; __half2* p_pre2; float* p_bnsum; float* p_bnsumsq; float* p_wp;
    cudaGetSymbolAddress((void**)&p_h,       g_h);
    cudaGetSymbolAddress((void**)&p_pre2,    g_pre2);
    cudaGetSymbolAddress((void**)&p_bnsum,   g_bnsum);
    cudaGetSymbolAddress((void**)&p_bnsumsq, g_bnsumsq);
    cudaGetSymbolAddress((void**)&p_wp,      g_Wpack);

    setup_persist<<<SGRID, STHREADS>>>(ei, batch, convW, E, N);

    int ntiles = (N + 63) / 64;
    int fgrid = ntiles < FGRID ? ntiles : FGRID;
    int agrid = (N + 63) / 64;

    fused_layer<<<fgrid, 256>>>(x, nullptr, nullptr, nullptr, nullptr,
                                nullptr, nullptr, nullptr, p_h, 0,
                                p_wp, invN, N);
    aggregate<<<agrid, 512>>>(convB, p_bnsum, p_bnsumsq, N);

    fused_layer<<<fgrid, 256>>>(nullptr, p_pre2, p_bnsum, p_bnsumsq,
                                bn_g, bn_b, ln_g, ln_b,
                                p_h, 0, p_wp + 4096, invN, N);
    aggregate<<<agrid, 512>>>(convB + 64, p_bnsum + 64, p_bnsumsq + 64, N);

    fused_layer<<<fgrid, 256>>>(nullptr, p_pre2, p_bnsum + 64, p_bnsumsq + 64,
                                bn_g + 64, bn_b + 64, ln_g + 64, ln_b + 64,
                                p_h, 1, p_wp + 2 * 4096, invN, N);
    aggregate<<<agrid, 512>>>(convB + 2 * 64, p_bnsum + 2 * 64, p_bnsumsq + 2 * 64, N);

    pool_mlp<<<G, 256>>>(p_bnsum + 2 * 64, p_bnsumsq + 2 * 64,
                         bn_g + 2 * 64, bn_b + 2 * 64,
                         ln_g + 2 * 64, ln_b + 2 * 64,
                         W1, b1, l1g, l1b, W2, b2, l2g, l2b, W3, b3, out, invN);
}

// round 14
// speedup vs baseline: 1.0516x; 1.0516x over previous
#include <cuda_runtime.h>
#include <cuda_fp16.h>
#include <float.h>
#include <math.h>

#define DMAX 64
#define NMAX 100000
#define EMAX 1600000
#define GMAX 512
#define LMAX 3
#define HS_STRIDE 68
#define SGRID 148
#define STHREADS 1024

// ---------------- scratch (no allocations allowed) ----------------
__device__ __align__(16) __half2 g_hws2[NMAX * 32];  // fp16 scaled conv output
__device__ __align__(16) __half2 g_pre2[NMAX * 32];  // fp16 pre-BN aggregates
__device__ float g_h[NMAX * DMAX];
__device__ float g_dinv[NMAX];
__device__ float g_Wpack[LMAX * 4096];               // tf32 W fragments
__device__ int   g_cnt[NMAX];
__device__ int   g_incl[NMAX];
__device__ int   g_rowptr[NMAX + 1];
__device__ int   g_wpos[NMAX];
__device__ int   g_srcs[EMAX];
__device__ int   g_part[128];
__device__ float g_bnsum[LMAX * DMAX], g_bnsumsq[LMAX * DMAX];
__device__ int   g_gcnt[GMAX];
__device__ int   g_goff[GMAX];
__device__ unsigned g_barrier;   // monotonic across uses AND graph replays

// ---------------- helpers ----------------
__device__ __forceinline__ float gelu_exact(float x) {
    return 0.5f * x * (1.0f + erff(x * 0.70710678118654752f));
}

__device__ __forceinline__ unsigned tf32cvt(float f) {
    unsigned r;
    asm("cvt.rna.tf32.f32 %0, %1;" : "=r"(r) : "f"(f));
    return r;
}

__device__ __forceinline__ void mma_tf32(float& c0, float& c1, float& c2, float& c3,
                                         unsigned a0, unsigned a1, unsigned a2,
                                         unsigned a3, unsigned b0, unsigned b1) {
    asm("mma.sync.aligned.m16n8k8.row.col.f32.tf32.tf32.f32 "
        "{%0,%1,%2,%3},{%4,%5,%6,%7},{%8,%9},{%0,%1,%2,%3};"
        : "+f"(c0), "+f"(c1), "+f"(c2), "+f"(c3)
        : "r"(a0), "r"(a1), "r"(a2), "r"(a3), "r"(b0), "r"(b1));
}

__device__ __forceinline__ void acc8(uint4 v, float* a) {
    float2 f;
    f = __half22float2(*(__half2*)&v.x); a[0] += f.x; a[1] += f.y;
    f = __half22float2(*(__half2*)&v.y); a[2] += f.x; a[3] += f.y;
    f = __half22float2(*(__half2*)&v.z); a[4] += f.x; a[5] += f.y;
    f = __half22float2(*(__half2*)&v.w); a[6] += f.x; a[7] += f.y;
}

__device__ __forceinline__ float wsum(float v) {
#pragma unroll
    for (int o = 16; o; o >>= 1) v += __shfl_xor_sync(0xffffffffu, v, o);
    return v;
}

// Monotonic-ticket grid barrier (148 blocks, guaranteed co-resident).
__device__ __forceinline__ void grid_bar() {
    __syncthreads();
    if (threadIdx.x == 0) {
        unsigned ticket;
        asm volatile("atom.add.release.gpu.u32 %0, [%1], %2;"
                     : "=r"(ticket) : "l"(&g_barrier), "r"(1u) : "memory");
        ticket += 1;
        unsigned goal = ((ticket - 1) / SGRID + 1) * SGRID;
        unsigned cur;
        do {
            asm volatile("ld.acquire.gpu.u32 %0, [%1];"
                         : "=r"(cur) : "l"(&g_barrier) : "memory");
        } while (cur < goal);
    }
    __syncthreads();
}

// ---------------- persistent setup: zero+hist+scan+place+Wpack ----------------
__global__ __launch_bounds__(STHREADS, 1) void setup_persist(
    const int* __restrict__ ei, const int* __restrict__ batch,
    const float* __restrict__ convW, int E, int n) {
    __shared__ int sh[STHREADS];
    const int t = threadIdx.x;
    const int b = blockIdx.x;
    const int gsz = SGRID * STHREADS;
    const int gtid = b * STHREADS + t;

    // phase 0: zero accumulators + pack tf32 W fragments
    for (int i = gtid; i < n; i += gsz) g_cnt[i] = 0;
    if (gtid < GMAX) g_gcnt[gtid] = 0;
    if (gtid < LMAX * DMAX) { g_bnsum[gtid] = 0.f; g_bnsumsq[gtid] = 0.f; }
    for (int idx = gtid; idx < LMAX * 2048; idx += gsz) {
        int L = idx >> 11, i = idx & 2047;
        int ks = i >> 8;
        int gsub = (i >> 5) & 7;
        int l = i & 31;
        int ltid = l & 3, lgid = l >> 2;
        const float* W = convW + L * 4096;
        unsigned b0 = tf32cvt(W[(ks * 8 + ltid) * 64 + gsub * 8 + lgid]);
        unsigned b1 = tf32cvt(W[(ks * 8 + ltid + 4) * 64 + gsub * 8 + lgid]);
        g_Wpack[L * 4096 + i * 2]     = __uint_as_float(b0);
        g_Wpack[L * 4096 + i * 2 + 1] = __uint_as_float(b1);
    }
    grid_bar();

    // phase 1: histograms
    for (int e = gtid; e < E; e += gsz) atomicAdd(&g_cnt[ei[E + e]], 1);
    for (int i = gtid; i < n; i += gsz) atomicAdd(&g_gcnt[batch[i]], 1);
    grid_bar();

    // phase 2: per-chunk inclusive scans (1024-wide)
    const int nchunk = (n + STHREADS - 1) / STHREADS;
    for (int c = b; c < nchunk; c += SGRID) {
        int i = c * STHREADS + t;
        int v = (i < n) ? g_cnt[i] : 0;
        sh[t] = v;
        __syncthreads();
        for (int o = 1; o < STHREADS; o <<= 1) {
            int u = (t >= o) ? sh[t - o] : 0;
            __syncthreads();
            sh[t] += u;
            __syncthreads();
        }
        if (i < n) g_incl[i] = sh[t];
        if (t == STHREADS - 1) g_part[c] = sh[STHREADS - 1];
        __syncthreads();
    }
    grid_bar();

    // phase 3: scan partials (block 0) + graph counts (block 1)
    if (b == 0) {
        if (t < 128) {
            int v = (t < nchunk) ? g_part[t] : 0;
            sh[t] = v;
            __syncthreads();
            for (int o = 1; o < 128; o <<= 1) {
                int u = (t >= o) ? sh[t - o] : 0;
                __syncthreads();
                sh[t] += u;
                __syncthreads();
            }
            g_part[t] = sh[t] - v;
        } else {
            for (int o = 1; o < 128; o <<= 1) { __syncthreads(); __syncthreads(); }
            __syncthreads();
        }
    } else if (b == 1) {
        if (t < GMAX) {
            int v = g_gcnt[t];
            sh[t] = v;
            __syncthreads();
            for (int o = 1; o < GMAX; o <<= 1) {
                int u = (t >= o) ? sh[t - o] : 0;
                __syncthreads();
                sh[t] += u;
                __syncthreads();
            }
            g_goff[t] = sh[t] - v;
        } else {
            for (int o = 1; o < GMAX; o <<= 1) { __syncthreads(); __syncthreads(); }
            __syncthreads();
        }
    }
    grid_bar();

    // phase 4: finish CSR rowptrs + dinv
    for (int i = gtid; i < n; i += gsz) {
        int c = g_cnt[i];
        int incl = g_incl[i] + g_part[i / STHREADS];
        int rp = incl - c;
        g_rowptr[i] = rp;
        g_wpos[i]   = rp;
        g_dinv[i]   = rsqrtf((float)(c + 1));
        if (i == n - 1) g_rowptr[n] = incl;
    }
    grid_bar();

    // phase 5: place edges
    for (int e = gtid; e < E; e += gsz) {
        int s = ei[e], d = ei[E + e];
        g_srcs[atomicAdd(&g_wpos[d], 1)] = s;
    }
}

// ---------------- fused layer: [BN+res+LN+GELU transform] + tf32 MMA GEMM -----
__global__ __launch_bounds__(256) void fused_layer(
    const float* __restrict__ xsrc,
    const __half2* __restrict__ pre2,
    const float* __restrict__ bnsum, const float* __restrict__ bnsumsq,
    const float* __restrict__ bng, const float* __restrict__ bnb,
    const float* __restrict__ lng, const float* __restrict__ lnb,
    float* __restrict__ hio, int useRes,
    const float* __restrict__ Wp, float invN, int n) {
    __shared__ float Bf[4096];                // prepacked B fragments
    __shared__ float Hs[64 * HS_STRIDE];      // tf32-converted H tile
    int t = threadIdx.x;
    int w = t >> 5, lane = t & 31;
    int gid = lane >> 2, tid = lane & 3;

    for (int i = t; i < 1024; i += 256)
        ((float4*)Bf)[i] = ((const float4*)Wp)[i];

    int row0 = blockIdx.x * 64;
    if (pre2 == nullptr) {
        for (int i = t; i < 1024; i += 256) {
            int r = i >> 4, q = i & 15;
            int row = row0 + r;
            float4 v = (row < n) ? __ldg(&((const float4*)xsrc)[row * 16 + q])
                                 : make_float4(0.f, 0.f, 0.f, 0.f);
            float* hp = &Hs[r * HS_STRIDE + q * 4];
            hp[0] = __uint_as_float(tf32cvt(v.x));
            hp[1] = __uint_as_float(tf32cvt(v.y));
            hp[2] = __uint_as_float(tf32cvt(v.z));
            hp[3] = __uint_as_float(tf32cvt(v.w));
        }
    } else {
        int f0 = 2 * lane, f1 = f0 + 1;
        float mu0 = bnsum[f0] * invN;
        float var0 = bnsumsq[f0] * invN - mu0 * mu0;
        float sc0 = rsqrtf(var0 + 1e-5f) * bng[f0];
        float sh0 = bnb[f0] - mu0 * sc0;
        float mu1 = bnsum[f1] * invN;
        float var1 = bnsumsq[f1] * invN - mu1 * mu1;
        float sc1 = rsqrtf(var1 + 1e-5f) * bng[f1];
        float sh1 = bnb[f1] - mu1 * sc1;
        float lg0 = lng[f0], lb0 = lnb[f0];
        float lg1 = lng[f1], lb1 = lnb[f1];
#pragma unroll
        for (int rr = 0; rr < 8; rr++) {
            int r = w * 8 + rr;
            int row = row0 + r;
            if (row < n) {
                float2 pv = __half22float2(pre2[row * 32 + lane]);
                float v0 = pv.x * sc0 + sh0;
                float v1 = pv.y * sc1 + sh1;
                if (useRes) {
                    float2 hv = ((const float2*)hio)[row * 32 + lane];
                    v0 += hv.x; v1 += hv.y;
                }
                float s = wsum(v0 + v1);
                float mu = s * (1.0f / 64.0f);
                float d0 = v0 - mu, d1 = v1 - mu;
                float vv = wsum(d0 * d0 + d1 * d1);
                float rstd = rsqrtf(vv * (1.0f / 64.0f) + 1e-5f);
                float y0 = gelu_exact(d0 * rstd * lg0 + lb0);
                float y1 = gelu_exact(d1 * rstd * lg1 + lb1);
                Hs[r * HS_STRIDE + f0] = __uint_as_float(tf32cvt(y0));
                Hs[r * HS_STRIDE + f1] = __uint_as_float(tf32cvt(y1));
                float2 st; st.x = y0; st.y = y1;
                ((float2*)hio)[row * 32 + lane] = st;
            } else {
                Hs[r * HS_STRIDE + f0] = 0.f;
                Hs[r * HS_STRIDE + f1] = 0.f;
            }
        }
    }
    __syncthreads();

    int m0 = (w & 3) * 16;
    int n0 = (w >> 2) * 32;
    float c[4][4];
#pragma unroll
    for (int s = 0; s < 4; s++)
#pragma unroll
        for (int j = 0; j < 4; j++) c[s][j] = 0.f;

    const float* Ar0 = &Hs[(m0 + gid) * HS_STRIDE];
    const float* Ar1 = &Hs[(m0 + gid + 8) * HS_STRIDE];
#pragma unroll
    for (int ks = 0; ks < 8; ks++) {
        int k0 = ks * 8;
        unsigned a0 = __float_as_uint(Ar0[k0 + tid]);
        unsigned a1 = __float_as_uint(Ar1[k0 + tid]);
        unsigned a2 = __float_as_uint(Ar0[k0 + tid + 4]);
        unsigned a3 = __float_as_uint(Ar1[k0 + tid + 4]);
#pragma unroll
        for (int s = 0; s < 4; s++) {
            int gsub = (n0 >> 3) + s;
            float2 b = *(const float2*)&Bf[((ks * 8 + gsub) * 32 + lane) * 2];
            mma_tf32(c[s][0], c[s][1], c[s][2], c[s][3],
                     a0, a1, a2, a3,
                     __float_as_uint(b.x), __float_as_uint(b.y));
        }
    }

    int rowa = row0 + m0 + gid;
    int rowb = rowa + 8;
    float dia = (rowa < n) ? g_dinv[rowa] : 0.f;
    float dib = (rowb < n) ? g_dinv[rowb] : 0.f;
    __half2* hw = (__half2*)g_hws2;
#pragma unroll
    for (int s = 0; s < 4; s++) {
        int col = n0 + s * 8 + tid * 2;
        if (rowa < n)
            hw[rowa * 32 + (col >> 1)] = __floats2half2_rn(c[s][0] * dia, c[s][1] * dia);
        if (rowb < n)
            hw[rowb * 32 + (col >> 1)] = __floats2half2_rn(c[s][2] * dib, c[s][3] * dib);
    }
}

// ---- CSR aggregate: 4 rows/warp, 8 lanes x 16B per row, MLP-4 gather ---------
__global__ __launch_bounds__(512) void aggregate(const float* __restrict__ convB,
                                                 float* __restrict__ bnsum,
                                                 float* __restrict__ bnsumsq,
                                                 int n) {
    __shared__ float bs[64], bs2[64];
    int t = threadIdx.x;
    if (t < 64) { bs[t] = 0.f; bs2[t] = 0.f; }
    __syncthreads();
    int warp = (blockIdx.x * 512 + t) >> 5;
    int lane = t & 31;
    int sub = lane & 7;
    int group = lane >> 3;
    int r = warp * 4 + group;
    float a[8];
#pragma unroll
    for (int j = 0; j < 8; j++) a[j] = 0.f;
    float psum[8], psq[8];
    bool valid = (r < n);
    if (valid) {
        const uint4* hw4 = (const uint4*)g_hws2;
        acc8(hw4[r * 8 + sub], a);   // self-loop
        int p0 = g_rowptr[r], p1 = g_rowptr[r + 1];
        int p = p0;
        // 4-way batched gather: 4 independent idx loads, then 4 independent
        // LDG.128 in flight before any accumulate (explicit MLP=4).
        for (; p + 3 < p1; p += 4) {
            int s0 = g_srcs[p];
            int s1 = g_srcs[p + 1];
            int s2 = g_srcs[p + 2];
            int s3 = g_srcs[p + 3];
            uint4 v0 = hw4[s0 * 8 + sub];
            uint4 v1 = hw4[s1 * 8 + sub];
            uint4 v2 = hw4[s2 * 8 + sub];
            uint4 v3 = hw4[s3 * 8 + sub];
            acc8(v0, a); acc8(v1, a); acc8(v2, a); acc8(v3, a);
        }
        for (; p < p1; p++) {
            int s = g_srcs[p];
            acc8(hw4[s * 8 + sub], a);
        }
        float di = g_dinv[r];
#pragma unroll
        for (int j = 0; j < 8; j++) {
            float pv = fmaf(di, a[j], convB[sub * 8 + j]);
            a[j] = pv;
            psum[j] = pv;
            psq[j] = pv * pv;
        }
        __half2 h0 = __floats2half2_rn(a[0], a[1]);
        __half2 h1 = __floats2half2_rn(a[2], a[3]);
        __half2 h2 = __floats2half2_rn(a[4], a[5]);
        __half2 h3 = __floats2half2_rn(a[6], a[7]);
        uint4 st;
        st.x = *(unsigned*)&h0; st.y = *(unsigned*)&h1;
        st.z = *(unsigned*)&h2; st.w = *(unsigned*)&h3;
        ((uint4*)g_pre2)[r * 8 + sub] = st;
    } else {
#pragma unroll
        for (int j = 0; j < 8; j++) { psum[j] = 0.f; psq[j] = 0.f; }
    }
#pragma unroll
    for (int j = 0; j < 8; j++) {
        psum[j] += __shfl_xor_sync(0xffffffffu, psum[j], 8);
        psq[j]  += __shfl_xor_sync(0xffffffffu, psq[j], 8);
        psum[j] += __shfl_xor_sync(0xffffffffu, psum[j], 16);
        psq[j]  += __shfl_xor_sync(0xffffffffu, psq[j], 16);
    }
    if (group == 0) {
#pragma unroll
        for (int j = 0; j < 8; j++) {
            atomicAdd(&bs[sub * 8 + j], psum[j]);
            atomicAdd(&bs2[sub * 8 + j], psq[j]);
        }
    }
    __syncthreads();
    if (t < 64) {
        atomicAdd(&bnsum[t], bs[t]);
        atomicAdd(&bnsumsq[t], bs2[t]);
    }
}

// ---- fused: final BN+res+LN+GELU transform + pool + MLP head per graph -------
__global__ __launch_bounds__(256) void pool_mlp(
    const float* __restrict__ bnsum, const float* __restrict__ bnsumsq,
    const float* __restrict__ bng, const float* __restrict__ bnb,
    const float* __restrict__ lng, const float* __restrict__ lnb,
    const float* __restrict__ W1, const float* __restrict__ b1,
    const float* __restrict__ l1g, const float* __restrict__ l1b,
    const float* __restrict__ W2, const float* __restrict__ b2,
    const float* __restrict__ l2g, const float* __restrict__ l2b,
    const float* __restrict__ W3, const float* __restrict__ b3,
    float* __restrict__ out, float invN) {
    int g = blockIdx.x, t = threadIdx.x;
    __shared__ float zs[192];
    __shared__ float shs[8][64], shm[8][64];
    __shared__ float s2[128];
    __shared__ float red[128];

    int start = g_goff[g], cnt = g_gcnt[g];
    int w = t >> 5, lane = t & 31;
    int f0 = 2 * lane, f1 = f0 + 1;

    float mu0 = bnsum[f0] * invN;
    float var0 = bnsumsq[f0] * invN - mu0 * mu0;
    float sc0 = rsqrtf(var0 + 1e-5f) * bng[f0];
    float sh0 = bnb[f0] - mu0 * sc0;
    float mu1 = bnsum[f1] * invN;
    float var1 = bnsumsq[f1] * invN - mu1 * mu1;
    float sc1 = rsqrtf(var1 + 1e-5f) * bng[f1];
    float sh1 = bnb[f1] - mu1 * sc1;
    float lg0 = lng[f0], lb0 = lnb[f0];
    float lg1 = lng[f1], lb1 = lnb[f1];

    float s0 = 0.f, s1 = 0.f, m0 = -FLT_MAX, m1 = -FLT_MAX;
    for (int r = start + w; r < start + cnt; r += 8) {
        float2 pv = __half22float2(g_pre2[r * 32 + lane]);
        float2 hv = ((const float2*)g_h)[r * 32 + lane];
        float v0 = pv.x * sc0 + sh0 + hv.x;
        float v1 = pv.y * sc1 + sh1 + hv.y;
        float s = wsum(v0 + v1);
        float mu = s * (1.0f / 64.0f);
        float d0 = v0 - mu, d1 = v1 - mu;
        float vv = wsum(d0 * d0 + d1 * d1);
        float rstd = rsqrtf(vv * (1.0f / 64.0f) + 1e-5f);
        float y0 = gelu_exact(d0 * rstd * lg0 + lb0);
        float y1 = gelu_exact(d1 * rstd * lg1 + lb1);
        s0 += y0; s1 += y1;
        m0 = fmaxf(m0, y0); m1 = fmaxf(m1, y1);
    }
    shs[w][f0] = s0; shs[w][f1] = s1;
    shm[w][f0] = m0; shm[w][f1] = m1;
    __syncthreads();
    if (t < 64) {
        float s = 0.f, m = -FLT_MAX;
#pragma unroll
        for (int k = 0; k < 8; k++) {
            s += shs[k][t];
            m = fmaxf(m, shm[k][t]);
        }
        float mean = (cnt > 0) ? s / (float)cnt : 0.f;
        if (cnt == 0) { m = 0.f; s = 0.f; }
        zs[t] = mean;
        zs[64 + t] = m;
        zs[128 + t] = s;
    }
    __syncthreads();

    float accv = 0.f;
    if (t < 128) {
        accv = b1[t];
#pragma unroll 4
        for (int k = 0; k < 192; k++) accv = fmaf(zs[k], W1[k * 128 + t], accv);
        red[t] = accv;
    }
    __syncthreads();
    if (t < 128) {
        for (int o = 64; o > 0; o >>= 1) {
            if (t < o) red[t] += red[t + o];
            __syncwarp(0xffffffffu);
            if (o > 32) __syncthreads();
        }
    }
    __syncthreads();
    float mu = red[0] * (1.0f / 128.0f);
    __syncthreads();
    float dv = accv - mu;
    if (t < 128) red[t] = dv * dv;
    __syncthreads();
    if (t < 128) {
        for (int o = 64; o > 0; o >>= 1) {
            if (t < o) red[t] += red[t + o];
            __syncwarp(0xffffffffu);
            if (o > 32) __syncthreads();
        }
    }
    __syncthreads();
    float rstd = rsqrtf(red[0] * (1.0f / 128.0f) + 1e-5f);
    __syncthreads();
    if (t < 128) s2[t] = gelu_exact(dv * rstd * l1g[t] + l1b[t]);
    __syncthreads();
    float acc2 = 0.f;
    if (t < 64) {
        acc2 = b2[t];
#pragma unroll 4
        for (int k = 0; k < 128; k++) acc2 = fmaf(s2[k], W2[k * 64 + t], acc2);
    }
    if (t < 128) red[t] = (t < 64) ? acc2 : 0.f;
    __syncthreads();
    if (t < 128) {
        for (int o = 64; o > 0; o >>= 1) {
            if (t < o) red[t] += red[t + o];
            __syncwarp(0xffffffffu);
            if (o > 32) __syncthreads();
        }
    }
    __syncthreads();
    float mu2 = red[0] * (1.0f / 64.0f);
    __syncthreads();
    float dv2 = acc2 - mu2;
    if (t < 128) red[t] = (t < 64) ? dv2 * dv2 : 0.f;
    __syncthreads();
    if (t < 128) {
        for (int o = 64; o > 0; o >>= 1) {
            if (t < o) red[t] += red[t + o];
            __syncwarp(0xffffffffu);
            if (o > 32) __syncthreads();
        }
    }
    __syncthreads();
    float rstd2 = rsqrtf(red[0] * (1.0f / 64.0f) + 1e-5f);
    __syncthreads();
    float y2 = 0.f;
    if (t < 64) y2 = gelu_exact(dv2 * rstd2 * l2g[t] + l2b[t]);
    if (t < 128) red[t] = (t < 64) ? y2 * W3[t] : 0.f;
    __syncthreads();
    if (t < 128) {
        for (int o = 64; o > 0; o >>= 1) {
            if (t < o) red[t] += red[t + o];
            __syncwarp(0xffffffffu);
            if (o > 32) __syncthreads();
        }
    }
    __syncthreads();
    if (t == 0) out[g] = red[0] + b3[0];
}

// ---------------- host ----------------
extern "C" void kernel_launch(void* const* d_in, const int* in_sizes, int n_in,
                              void* d_out, int out_size) {
    const float* x     = (const float*)d_in[0];
    const int*   ei    = (const int*)d_in[1];
    const int*   batch = (const int*)d_in[2];
    const float* convW = (const float*)d_in[3];
    const float* convB = (const float*)d_in[4];
    const float* bn_g  = (const float*)d_in[5];
    const float* bn_b  = (const float*)d_in[6];
    const float* ln_g  = (const float*)d_in[7];
    const float* ln_b  = (const float*)d_in[8];
    const float* W1    = (const float*)d_in[9];
    const float* b1    = (const float*)d_in[10];
    const float* l1g   = (const float*)d_in[11];
    const float* l1b   = (const float*)d_in[12];
    const float* W2    = (const float*)d_in[13];
    const float* b2    = (const float*)d_in[14];
    const float* l2g   = (const float*)d_in[15];
    const float* l2b   = (const float*)d_in[16];
    const float* W3    = (const float*)d_in[17];
    const float* b3    = (const float*)d_in[18];
    float* out = (float*)d_out;

    const int N = in_sizes[0] / 64;
    const int E = in_sizes[1] / 2;
    const int G = out_size;
    const float invN = 1.0f / (float)N;

    float* p_h; __half2* p_pre2; float* p_bnsum; float* p_bnsumsq; float* p_wp;
    cudaGetSymbolAddress((void**)&p_h,       g_h);
    cudaGetSymbolAddress((void**)&p_pre2,    g_pre2);
    cudaGetSymbolAddress((void**)&p_bnsum,   g_bnsum);
    cudaGetSymbolAddress((void**)&p_bnsumsq, g_bnsumsq);
    cudaGetSymbolAddress((void**)&p_wp,      g_Wpack);

    setup_persist<<<SGRID, STHREADS>>>(ei, batch, convW, E, N);

    int fgrid = (N + 63) / 64;
    int agrid = (N + 63) / 64;

    fused_layer<<<fgrid, 256>>>(x, nullptr, nullptr, nullptr, nullptr,
                                nullptr, nullptr, nullptr, p_h, 0,
                                p_wp, invN, N);
    aggregate<<<agrid, 512>>>(convB, p_bnsum, p_bnsumsq, N);

    fused_layer<<<fgrid, 256>>>(nullptr, p_pre2, p_bnsum, p_bnsumsq,
                                bn_g, bn_b, ln_g, ln_b,
                                p_h, 0, p_wp + 4096, invN, N);
    aggregate<<<agrid, 512>>>(convB + 64, p_bnsum + 64, p_bnsumsq + 64, N);

    fused_layer<<<fgrid, 256>>>(nullptr, p_pre2, p_bnsum + 64, p_bnsumsq + 64,
                                bn_g + 64, bn_b + 64, ln_g + 64, ln_b + 64,
                                p_h, 1, p_wp + 2 * 4096, invN, N);
    aggregate<<<agrid, 512>>>(convB + 2 * 64, p_bnsum + 2 * 64, p_bnsumsq + 2 * 64, N);

    pool_mlp<<<G, 256>>>(p_bnsum + 2 * 64, p_bnsumsq + 2 * 64,
                         bn_g + 2 * 64, bn_b + 2 * 64,
                         ln_g + 2 * 64, ln_b + 2 * 64,
                         W1, b1, l1g, l1b, W2, b2, l2g, l2b, W3, b3, out, invN);
}

// round 15
// speedup vs baseline: 1.0588x; 1.0069x over previous
#include <cuda_runtime.h>
#include <cuda_fp16.h>
#include <float.h>
#include <math.h>

#define DMAX 64
#define NMAX 100000
#define EMAX 1600000
#define GMAX 512
#define LMAX 3
#define HS_STRIDE 68
#define SGRID 148
#define STHREADS 1024

// ---------------- scratch (no allocations allowed) ----------------
__device__ __align__(16) __half2 g_hws2[NMAX * 32];  // fp16 scaled conv output
__device__ __align__(16) __half2 g_pre2[NMAX * 32];  // fp16 pre-BN aggregates
__device__ __align__(16) __half2 g_h2[NMAX * 32];    // fp16 hidden state
__device__ float g_dinv[NMAX];
__device__ float g_Wpack[LMAX * 4096];               // tf32 W fragments
__device__ int   g_cnt[NMAX];
__device__ int   g_incl[NMAX];
__device__ int   g_rowptr[NMAX + 1];
__device__ int   g_wpos[NMAX];
__device__ int   g_srcs[EMAX];
__device__ int   g_part[128];
__device__ float g_bnsum[LMAX * DMAX], g_bnsumsq[LMAX * DMAX];
__device__ int   g_gcnt[GMAX];
__device__ int   g_goff[GMAX];
__device__ unsigned g_barrier;   // monotonic across uses AND graph replays

// ---------------- helpers ----------------
__device__ __forceinline__ float gelu_exact(float x) {
    return 0.5f * x * (1.0f + erff(x * 0.70710678118654752f));
}

__device__ __forceinline__ unsigned tf32cvt(float f) {
    unsigned r;
    asm("cvt.rna.tf32.f32 %0, %1;" : "=r"(r) : "f"(f));
    return r;
}

__device__ __forceinline__ void mma_tf32(float& c0, float& c1, float& c2, float& c3,
                                         unsigned a0, unsigned a1, unsigned a2,
                                         unsigned a3, unsigned b0, unsigned b1) {
    asm("mma.sync.aligned.m16n8k8.row.col.f32.tf32.tf32.f32 "
        "{%0,%1,%2,%3},{%4,%5,%6,%7},{%8,%9},{%0,%1,%2,%3};"
        : "+f"(c0), "+f"(c1), "+f"(c2), "+f"(c3)
        : "r"(a0), "r"(a1), "r"(a2), "r"(a3), "r"(b0), "r"(b1));
}

__device__ __forceinline__ void acc8(uint4 v, float* a) {
    float2 f;
    f = __half22float2(*(__half2*)&v.x); a[0] += f.x; a[1] += f.y;
    f = __half22float2(*(__half2*)&v.y); a[2] += f.x; a[3] += f.y;
    f = __half22float2(*(__half2*)&v.z); a[4] += f.x; a[5] += f.y;
    f = __half22float2(*(__half2*)&v.w); a[6] += f.x; a[7] += f.y;
}

__device__ __forceinline__ float wsum(float v) {
#pragma unroll
    for (int o = 16; o; o >>= 1) v += __shfl_xor_sync(0xffffffffu, v, o);
    return v;
}

// Monotonic-ticket grid barrier (148 blocks, guaranteed co-resident).
__device__ __forceinline__ void grid_bar() {
    __syncthreads();
    if (threadIdx.x == 0) {
        unsigned ticket;
        asm volatile("atom.add.release.gpu.u32 %0, [%1], %2;"
                     : "=r"(ticket) : "l"(&g_barrier), "r"(1u) : "memory");
        ticket += 1;
        unsigned goal = ((ticket - 1) / SGRID + 1) * SGRID;
        unsigned cur;
        do {
            asm volatile("ld.acquire.gpu.u32 %0, [%1];"
                         : "=r"(cur) : "l"(&g_barrier) : "memory");
        } while (cur < goal);
    }
    __syncthreads();
}

// ---------------- persistent setup: zero+hist+scan+place+Wpack ----------------
__global__ __launch_bounds__(STHREADS, 1) void setup_persist(
    const int* __restrict__ ei, const int* __restrict__ batch,
    const float* __restrict__ convW, int E, int n) {
    __shared__ int sh[STHREADS];
    const int t = threadIdx.x;
    const int b = blockIdx.x;
    const int gsz = SGRID * STHREADS;
    const int gtid = b * STHREADS + t;

    // phase 0: zero accumulators + pack tf32 W fragments
    for (int i = gtid; i < n; i += gsz) g_cnt[i] = 0;
    if (gtid < GMAX) g_gcnt[gtid] = 0;
    if (gtid < LMAX * DMAX) { g_bnsum[gtid] = 0.f; g_bnsumsq[gtid] = 0.f; }
    for (int idx = gtid; idx < LMAX * 2048; idx += gsz) {
        int L = idx >> 11, i = idx & 2047;
        int ks = i >> 8;
        int gsub = (i >> 5) & 7;
        int l = i & 31;
        int ltid = l & 3, lgid = l >> 2;
        const float* W = convW + L * 4096;
        unsigned b0 = tf32cvt(W[(ks * 8 + ltid) * 64 + gsub * 8 + lgid]);
        unsigned b1 = tf32cvt(W[(ks * 8 + ltid + 4) * 64 + gsub * 8 + lgid]);
        g_Wpack[L * 4096 + i * 2]     = __uint_as_float(b0);
        g_Wpack[L * 4096 + i * 2 + 1] = __uint_as_float(b1);
    }
    grid_bar();

    // phase 1: histograms
    for (int e = gtid; e < E; e += gsz) atomicAdd(&g_cnt[ei[E + e]], 1);
    for (int i = gtid; i < n; i += gsz) atomicAdd(&g_gcnt[batch[i]], 1);
    grid_bar();

    // phase 2: per-chunk inclusive scans (1024-wide)
    const int nchunk = (n + STHREADS - 1) / STHREADS;
    for (int c = b; c < nchunk; c += SGRID) {
        int i = c * STHREADS + t;
        int v = (i < n) ? g_cnt[i] : 0;
        sh[t] = v;
        __syncthreads();
        for (int o = 1; o < STHREADS; o <<= 1) {
            int u = (t >= o) ? sh[t - o] : 0;
            __syncthreads();
            sh[t] += u;
            __syncthreads();
        }
        if (i < n) g_incl[i] = sh[t];
        if (t == STHREADS - 1) g_part[c] = sh[STHREADS - 1];
        __syncthreads();
    }
    grid_bar();

    // phase 3: scan partials (block 0) + graph counts (block 1)
    if (b == 0) {
        if (t < 128) {
            int v = (t < nchunk) ? g_part[t] : 0;
            sh[t] = v;
            __syncthreads();
            for (int o = 1; o < 128; o <<= 1) {
                int u = (t >= o) ? sh[t - o] : 0;
                __syncthreads();
                sh[t] += u;
                __syncthreads();
            }
            g_part[t] = sh[t] - v;
        } else {
            for (int o = 1; o < 128; o <<= 1) { __syncthreads(); __syncthreads(); }
            __syncthreads();
        }
    } else if (b == 1) {
        if (t < GMAX) {
            int v = g_gcnt[t];
            sh[t] = v;
            __syncthreads();
            for (int o = 1; o < GMAX; o <<= 1) {
                int u = (t >= o) ? sh[t - o] : 0;
                __syncthreads();
                sh[t] += u;
                __syncthreads();
            }
            g_goff[t] = sh[t] - v;
        } else {
            for (int o = 1; o < GMAX; o <<= 1) { __syncthreads(); __syncthreads(); }
            __syncthreads();
        }
    }
    grid_bar();

    // phase 4: finish CSR rowptrs + dinv
    for (int i = gtid; i < n; i += gsz) {
        int c = g_cnt[i];
        int incl = g_incl[i] + g_part[i / STHREADS];
        int rp = incl - c;
        g_rowptr[i] = rp;
        g_wpos[i]   = rp;
        g_dinv[i]   = rsqrtf((float)(c + 1));
        if (i == n - 1) g_rowptr[n] = incl;
    }
    grid_bar();

    // phase 5: place edges
    for (int e = gtid; e < E; e += gsz) {
        int s = ei[e], d = ei[E + e];
        g_srcs[atomicAdd(&g_wpos[d], 1)] = s;
    }
}

// ---------------- fused layer: [BN+res+LN+GELU transform] + tf32 MMA GEMM -----
__global__ __launch_bounds__(256) void fused_layer(
    const float* __restrict__ xsrc,
    const __half2* __restrict__ pre2,
    const float* __restrict__ bnsum, const float* __restrict__ bnsumsq,
    const float* __restrict__ bng, const float* __restrict__ bnb,
    const float* __restrict__ lng, const float* __restrict__ lnb,
    __half2* __restrict__ hio2, int useRes,
    const float* __restrict__ Wp, float invN, int n) {
    __shared__ float Bf[4096];                // prepacked B fragments
    __shared__ float Hs[64 * HS_STRIDE];      // tf32-converted H tile
    int t = threadIdx.x;
    int w = t >> 5, lane = t & 31;
    int gid = lane >> 2, tid = lane & 3;

    for (int i = t; i < 1024; i += 256)
        ((float4*)Bf)[i] = ((const float4*)Wp)[i];

    int row0 = blockIdx.x * 64;
    if (pre2 == nullptr) {
        for (int i = t; i < 1024; i += 256) {
            int r = i >> 4, q = i & 15;
            int row = row0 + r;
            float4 v = (row < n) ? __ldg(&((const float4*)xsrc)[row * 16 + q])
                                 : make_float4(0.f, 0.f, 0.f, 0.f);
            float* hp = &Hs[r * HS_STRIDE + q * 4];
            hp[0] = __uint_as_float(tf32cvt(v.x));
            hp[1] = __uint_as_float(tf32cvt(v.y));
            hp[2] = __uint_as_float(tf32cvt(v.z));
            hp[3] = __uint_as_float(tf32cvt(v.w));
        }
    } else {
        int f0 = 2 * lane, f1 = f0 + 1;
        float mu0 = bnsum[f0] * invN;
        float var0 = bnsumsq[f0] * invN - mu0 * mu0;
        float sc0 = rsqrtf(var0 + 1e-5f) * bng[f0];
        float sh0 = bnb[f0] - mu0 * sc0;
        float mu1 = bnsum[f1] * invN;
        float var1 = bnsumsq[f1] * invN - mu1 * mu1;
        float sc1 = rsqrtf(var1 + 1e-5f) * bng[f1];
        float sh1 = bnb[f1] - mu1 * sc1;
        float lg0 = lng[f0], lb0 = lnb[f0];
        float lg1 = lng[f1], lb1 = lnb[f1];
#pragma unroll
        for (int rr = 0; rr < 8; rr++) {
            int r = w * 8 + rr;
            int row = row0 + r;
            if (row < n) {
                float2 pv = __half22float2(pre2[row * 32 + lane]);
                float v0 = pv.x * sc0 + sh0;
                float v1 = pv.y * sc1 + sh1;
                if (useRes) {
                    float2 hv = __half22float2(hio2[row * 32 + lane]);
                    v0 += hv.x; v1 += hv.y;
                }
                float s = wsum(v0 + v1);
                float mu = s * (1.0f / 64.0f);
                float d0 = v0 - mu, d1 = v1 - mu;
                float vv = wsum(d0 * d0 + d1 * d1);
                float rstd = rsqrtf(vv * (1.0f / 64.0f) + 1e-5f);
                float y0 = gelu_exact(d0 * rstd * lg0 + lb0);
                float y1 = gelu_exact(d1 * rstd * lg1 + lb1);
                Hs[r * HS_STRIDE + f0] = __uint_as_float(tf32cvt(y0));
                Hs[r * HS_STRIDE + f1] = __uint_as_float(tf32cvt(y1));
                hio2[row * 32 + lane] = __floats2half2_rn(y0, y1);
            } else {
                Hs[r * HS_STRIDE + f0] = 0.f;
                Hs[r * HS_STRIDE + f1] = 0.f;
            }
        }
    }
    __syncthreads();

    int m0 = (w & 3) * 16;
    int n0 = (w >> 2) * 32;
    float c[4][4];
#pragma unroll
    for (int s = 0; s < 4; s++)
#pragma unroll
        for (int j = 0; j < 4; j++) c[s][j] = 0.f;

    const float* Ar0 = &Hs[(m0 + gid) * HS_STRIDE];
    const float* Ar1 = &Hs[(m0 + gid + 8) * HS_STRIDE];
#pragma unroll
    for (int ks = 0; ks < 8; ks++) {
        int k0 = ks * 8;
        unsigned a0 = __float_as_uint(Ar0[k0 + tid]);
        unsigned a1 = __float_as_uint(Ar1[k0 + tid]);
        unsigned a2 = __float_as_uint(Ar0[k0 + tid + 4]);
        unsigned a3 = __float_as_uint(Ar1[k0 + tid + 4]);
#pragma unroll
        for (int s = 0; s < 4; s++) {
            int gsub = (n0 >> 3) + s;
            float2 b = *(const float2*)&Bf[((ks * 8 + gsub) * 32 + lane) * 2];
            mma_tf32(c[s][0], c[s][1], c[s][2], c[s][3],
                     a0, a1, a2, a3,
                     __float_as_uint(b.x), __float_as_uint(b.y));
        }
    }

    int rowa = row0 + m0 + gid;
    int rowb = rowa + 8;
    float dia = (rowa < n) ? g_dinv[rowa] : 0.f;
    float dib = (rowb < n) ? g_dinv[rowb] : 0.f;
    __half2* hw = (__half2*)g_hws2;
#pragma unroll
    for (int s = 0; s < 4; s++) {
        int col = n0 + s * 8 + tid * 2;
        if (rowa < n)
            hw[rowa * 32 + (col >> 1)] = __floats2half2_rn(c[s][0] * dia, c[s][1] * dia);
        if (rowb < n)
            hw[rowb * 32 + (col >> 1)] = __floats2half2_rn(c[s][2] * dib, c[s][3] * dib);
    }
}

// ---- CSR aggregate: 4 rows/warp, 8 lanes x 16B per row, + BN partials --------
__global__ __launch_bounds__(512) void aggregate(const float* __restrict__ convB,
                                                 float* __restrict__ bnsum,
                                                 float* __restrict__ bnsumsq,
                                                 int n) {
    __shared__ float bs[64], bs2[64];
    int t = threadIdx.x;
    if (t < 64) { bs[t] = 0.f; bs2[t] = 0.f; }
    __syncthreads();
    int warp = (blockIdx.x * 512 + t) >> 5;
    int lane = t & 31;
    int sub = lane & 7;
    int group = lane >> 3;
    int r = warp * 4 + group;
    float a[8];
#pragma unroll
    for (int j = 0; j < 8; j++) a[j] = 0.f;
    float psum[8], psq[8];
    bool valid = (r < n);
    if (valid) {
        acc8(((const uint4*)g_hws2)[r * 8 + sub], a);
        int p0 = g_rowptr[r], p1 = g_rowptr[r + 1];
#pragma unroll 4
        for (int p = p0; p < p1; p++) {
            int s = g_srcs[p];
            acc8(((const uint4*)g_hws2)[s * 8 + sub], a);
        }
        float di = g_dinv[r];
#pragma unroll
        for (int j = 0; j < 8; j++) {
            float pv = fmaf(di, a[j], convB[sub * 8 + j]);
            a[j] = pv;
            psum[j] = pv;
            psq[j] = pv * pv;
        }
        __half2 h0 = __floats2half2_rn(a[0], a[1]);
        __half2 h1 = __floats2half2_rn(a[2], a[3]);
        __half2 h2 = __floats2half2_rn(a[4], a[5]);
        __half2 h3 = __floats2half2_rn(a[6], a[7]);
        uint4 st;
        st.x = *(unsigned*)&h0; st.y = *(unsigned*)&h1;
        st.z = *(unsigned*)&h2; st.w = *(unsigned*)&h3;
        ((uint4*)g_pre2)[r * 8 + sub] = st;
    } else {
#pragma unroll
        for (int j = 0; j < 8; j++) { psum[j] = 0.f; psq[j] = 0.f; }
    }
#pragma unroll
    for (int j = 0; j < 8; j++) {
        psum[j] += __shfl_xor_sync(0xffffffffu, psum[j], 8);
        psq[j]  += __shfl_xor_sync(0xffffffffu, psq[j], 8);
        psum[j] += __shfl_xor_sync(0xffffffffu, psum[j], 16);
        psq[j]  += __shfl_xor_sync(0xffffffffu, psq[j], 16);
    }
    if (group == 0) {
#pragma unroll
        for (int j = 0; j < 8; j++) {
            atomicAdd(&bs[sub * 8 + j], psum[j]);
            atomicAdd(&bs2[sub * 8 + j], psq[j]);
        }
    }
    __syncthreads();
    if (t < 64) {
        atomicAdd(&bnsum[t], bs[t]);
        atomicAdd(&bnsumsq[t], bs2[t]);
    }
}

// ---- fused: final BN+res+LN+GELU transform + pool + MLP head per graph -------
__global__ __launch_bounds__(256) void pool_mlp(
    const float* __restrict__ bnsum, const float* __restrict__ bnsumsq,
    const float* __restrict__ bng, const float* __restrict__ bnb,
    const float* __restrict__ lng, const float* __restrict__ lnb,
    const float* __restrict__ W1, const float* __restrict__ b1,
    const float* __restrict__ l1g, const float* __restrict__ l1b,
    const float* __restrict__ W2, const float* __restrict__ b2,
    const float* __restrict__ l2g, const float* __restrict__ l2b,
    const float* __restrict__ W3, const float* __restrict__ b3,
    float* __restrict__ out, float invN) {
    int g = blockIdx.x, t = threadIdx.x;
    __shared__ float zs[192];
    __shared__ float shs[8][64], shm[8][64];
    __shared__ float s2[128];
    __shared__ float red[128];

    int start = g_goff[g], cnt = g_gcnt[g];
    int w = t >> 5, lane = t & 31;
    int f0 = 2 * lane, f1 = f0 + 1;

    float mu0 = bnsum[f0] * invN;
    float var0 = bnsumsq[f0] * invN - mu0 * mu0;
    float sc0 = rsqrtf(var0 + 1e-5f) * bng[f0];
    float sh0 = bnb[f0] - mu0 * sc0;
    float mu1 = bnsum[f1] * invN;
    float var1 = bnsumsq[f1] * invN - mu1 * mu1;
    float sc1 = rsqrtf(var1 + 1e-5f) * bng[f1];
    float sh1 = bnb[f1] - mu1 * sc1;
    float lg0 = lng[f0], lb0 = lnb[f0];
    float lg1 = lng[f1], lb1 = lnb[f1];

    float s0 = 0.f, s1 = 0.f, m0 = -FLT_MAX, m1 = -FLT_MAX;
    for (int r = start + w; r < start + cnt; r += 8) {
        float2 pv = __half22float2(g_pre2[r * 32 + lane]);
        float2 hv = __half22float2(g_h2[r * 32 + lane]);
        float v0 = pv.x * sc0 + sh0 + hv.x;
        float v1 = pv.y * sc1 + sh1 + hv.y;
        float s = wsum(v0 + v1);
        float mu = s * (1.0f / 64.0f);
        float d0 = v0 - mu, d1 = v1 - mu;
        float vv = wsum(d0 * d0 + d1 * d1);
        float rstd = rsqrtf(vv * (1.0f / 64.0f) + 1e-5f);
        float y0 = gelu_exact(d0 * rstd * lg0 + lb0);
        float y1 = gelu_exact(d1 * rstd * lg1 + lb1);
        s0 += y0; s1 += y1;
        m0 = fmaxf(m0, y0); m1 = fmaxf(m1, y1);
    }
    shs[w][f0] = s0; shs[w][f1] = s1;
    shm[w][f0] = m0; shm[w][f1] = m1;
    __syncthreads();
    if (t < 64) {
        float s = 0.f, m = -FLT_MAX;
#pragma unroll
        for (int k = 0; k < 8; k++) {
            s += shs[k][t];
            m = fmaxf(m, shm[k][t]);
        }
        float mean = (cnt > 0) ? s / (float)cnt : 0.f;
        if (cnt == 0) { m = 0.f; s = 0.f; }
        zs[t] = mean;
        zs[64 + t] = m;
        zs[128 + t] = s;
    }
    __syncthreads();

    float accv = 0.f;
    if (t < 128) {
        accv = b1[t];
#pragma unroll 4
        for (int k = 0; k < 192; k++) accv = fmaf(zs[k], W1[k * 128 + t], accv);
        red[t] = accv;
    }
    __syncthreads();
    if (t < 128) {
        for (int o = 64; o > 0; o >>= 1) {
            if (t < o) red[t] += red[t + o];
            __syncwarp(0xffffffffu);
            if (o > 32) __syncthreads();
        }
    }
    __syncthreads();
    float mu = red[0] * (1.0f / 128.0f);
    __syncthreads();
    float dv = accv - mu;
    if (t < 128) red[t] = dv * dv;
    __syncthreads();
    if (t < 128) {
        for (int o = 64; o > 0; o >>= 1) {
            if (t < o) red[t] += red[t + o];
            __syncwarp(0xffffffffu);
            if (o > 32) __syncthreads();
        }
    }
    __syncthreads();
    float rstd = rsqrtf(red[0] * (1.0f / 128.0f) + 1e-5f);
    __syncthreads();
    if (t < 128) s2[t] = gelu_exact(dv * rstd * l1g[t] + l1b[t]);
    __syncthreads();
    float acc2 = 0.f;
    if (t < 64) {
        acc2 = b2[t];
#pragma unroll 4
        for (int k = 0; k < 128; k++) acc2 = fmaf(s2[k], W2[k * 64 + t], acc2);
    }
    if (t < 128) red[t] = (t < 64) ? acc2 : 0.f;
    __syncthreads();
    if (t < 128) {
        for (int o = 64; o > 0; o >>= 1) {
            if (t < o) red[t] += red[t + o];
            __syncwarp(0xffffffffu);
            if (o > 32) __syncthreads();
        }
    }
    __syncthreads();
    float mu2 = red[0] * (1.0f / 64.0f);
    __syncthreads();
    float dv2 = acc2 - mu2;
    if (t < 128) red[t] = (t < 64) ? dv2 * dv2 : 0.f;
    __syncthreads();
    if (t < 128) {
        for (int o = 64; o > 0; o >>= 1) {
            if (t < o) red[t] += red[t + o];
            __syncwarp(0xffffffffu);
            if (o > 32) __syncthreads();
        }
    }
    __syncthreads();
    float rstd2 = rsqrtf(red[0] * (1.0f / 64.0f) + 1e-5f);
    __syncthreads();
    float y2 = 0.f;
    if (t < 64) y2 = gelu_exact(dv2 * rstd2 * l2g[t] + l2b[t]);
    if (t < 128) red[t] = (t < 64) ? y2 * W3[t] : 0.f;
    __syncthreads();
    if (t < 128) {
        for (int o = 64; o > 0; o >>= 1) {
            if (t < o) red[t] += red[t + o];
            __syncwarp(0xffffffffu);
            if (o > 32) __syncthreads();
        }
    }
    __syncthreads();
    if (t == 0) out[g] = red[0] + b3[0];
}

// ---------------- host ----------------
extern "C" void kernel_launch(void* const* d_in, const int* in_sizes, int n_in,
                              void* d_out, int out_size) {
    const float* x     = (const float*)d_in[0];
    const int*   ei    = (const int*)d_in[1];
    const int*   batch = (const int*)d_in[2];
    const float* convW = (const float*)d_in[3];
    const float* convB = (const float*)d_in[4];
    const float* bn_g  = (const float*)d_in[5];
    const float* bn_b  = (const float*)d_in[6];
    const float* ln_g  = (const float*)d_in[7];
    const float* ln_b  = (const float*)d_in[8];
    const float* W1    = (const float*)d_in[9];
    const float* b1    = (const float*)d_in[10];
    const float* l1g   = (const float*)d_in[11];
    const float* l1b   = (const float*)d_in[12];
    const float* W2    = (const float*)d_in[13];
    const float* b2    = (const float*)d_in[14];
    const float* l2g   = (const float*)d_in[15];
    const float* l2b   = (const float*)d_in[16];
    const float* W3    = (const float*)d_in[17];
    const float* b3    = (const float*)d_in[18];
    float* out = (float*)d_out;

    const int N = in_sizes[0] / 64;
    const int E = in_sizes[1] / 2;
    const int G = out_size;
    const float invN = 1.0f / (float)N;

    __half2* p_h2; __half2* p_pre2; float* p_bnsum; float* p_bnsumsq; float* p_wp;
    cudaGetSymbolAddress((void**)&p_h2,      g_h2);
    cudaGetSymbolAddress((void**)&p_pre2,    g_pre2);
    cudaGetSymbolAddress((void**)&p_bnsum,   g_bnsum);
    cudaGetSymbolAddress((void**)&p_bnsumsq, g_bnsumsq);
    cudaGetSymbolAddress((void**)&p_wp,      g_Wpack);

    setup_persist<<<SGRID, STHREADS>>>(ei, batch, convW, E, N);

    int fgrid = (N + 63) / 64;
    int agrid = (N + 63) / 64;

    fused_layer<<<fgrid, 256>>>(x, nullptr, nullptr, nullptr, nullptr,
                                nullptr, nullptr, nullptr, p_h2, 0,
                                p_wp, invN, N);
    aggregate<<<agrid, 512>>>(convB, p_bnsum, p_bnsumsq, N);

    fused_layer<<<fgrid, 256>>>(nullptr, p_pre2, p_bnsum, p_bnsumsq,
                                bn_g, bn_b, ln_g, ln_b,
                                p_h2, 0, p_wp + 4096, invN, N);
    aggregate<<<agrid, 512>>>(convB + 64, p_bnsum + 64, p_bnsumsq + 64, N);

    fused_layer<<<fgrid, 256>>>(nullptr, p_pre2, p_bnsum + 64, p_bnsumsq + 64,
                                bn_g + 64, bn_b + 64, ln_g + 64, ln_b + 64,
                                p_h2, 1, p_wp + 2 * 4096, invN, N);
    aggregate<<<agrid, 512>>>(convB + 2 * 64, p_bnsum + 2 * 64, p_bnsumsq + 2 * 64, N);

    pool_mlp<<<G, 256>>>(p_bnsum + 2 * 64, p_bnsumsq + 2 * 64,
                         bn_g + 2 * 64, bn_b + 2 * 64,
                         ln_g + 2 * 64, ln_b + 2 * 64,
                         W1, b1, l1g, l1b, W2, b2, l2g, l2b, W3, b3, out, invN);
}

// round 16
// speedup vs baseline: 1.1227x; 1.0603x over previous
#include <cuda_runtime.h>
#include <cuda_fp16.h>
#include <float.h>
#include <math.h>

#define DMAX 64
#define NMAX 100000
#define EMAX 1600000
#define GMAX 512
#define LMAX 3
#define HSW 36            // Hs row stride in 32-bit words (72 halves)
#define SGRID 148
#define STHREADS 1024

// ---------------- scratch (no allocations allowed) ----------------
__device__ __align__(16) __half2 g_hws2[NMAX * 32];  // fp16 scaled conv output
__device__ __align__(16) __half2 g_pre2[NMAX * 32];  // fp16 pre-BN aggregates
__device__ float g_h[NMAX * DMAX];
__device__ float g_dinv[NMAX];
__device__ __align__(16) unsigned g_Wpack[LMAX * 2048]; // fp16 W fragments (half2)
__device__ int   g_cnt[NMAX];
__device__ int   g_incl[NMAX];
__device__ int   g_rowptr[NMAX + 1];
__device__ int   g_wpos[NMAX];
__device__ int   g_srcs[EMAX];
__device__ int   g_part[128];
__device__ float g_bnsum[LMAX * DMAX], g_bnsumsq[LMAX * DMAX];
__device__ int   g_gcnt[GMAX];
__device__ int   g_goff[GMAX];
__device__ unsigned g_barrier;   // monotonic across uses AND graph replays

// ---------------- helpers ----------------
__device__ __forceinline__ float gelu_exact(float x) {
    return 0.5f * x * (1.0f + erff(x * 0.70710678118654752f));
}

__device__ __forceinline__ unsigned packh2(float lo, float hi) {
    __half2 h = __floats2half2_rn(lo, hi);
    return *(unsigned*)&h;
}

// m16n8k16 fp16 MMA, fp32 accumulate
__device__ __forceinline__ void mma_f16(float& c0, float& c1, float& c2, float& c3,
                                        unsigned a0, unsigned a1, unsigned a2,
                                        unsigned a3, unsigned b0, unsigned b1) {
    asm("mma.sync.aligned.m16n8k16.row.col.f32.f16.f16.f32 "
        "{%0,%1,%2,%3},{%4,%5,%6,%7},{%8,%9},{%0,%1,%2,%3};"
        : "+f"(c0), "+f"(c1), "+f"(c2), "+f"(c3)
        : "r"(a0), "r"(a1), "r"(a2), "r"(a3), "r"(b0), "r"(b1));
}

__device__ __forceinline__ void acc8(uint4 v, float* a) {
    float2 f;
    f = __half22float2(*(__half2*)&v.x); a[0] += f.x; a[1] += f.y;
    f = __half22float2(*(__half2*)&v.y); a[2] += f.x; a[3] += f.y;
    f = __half22float2(*(__half2*)&v.z); a[4] += f.x; a[5] += f.y;
    f = __half22float2(*(__half2*)&v.w); a[6] += f.x; a[7] += f.y;
}

__device__ __forceinline__ float wsum(float v) {
#pragma unroll
    for (int o = 16; o; o >>= 1) v += __shfl_xor_sync(0xffffffffu, v, o);
    return v;
}

// Monotonic-ticket grid barrier (148 blocks, guaranteed co-resident).
__device__ __forceinline__ void grid_bar() {
    __syncthreads();
    if (threadIdx.x == 0) {
        unsigned ticket;
        asm volatile("atom.add.release.gpu.u32 %0, [%1], %2;"
                     : "=r"(ticket) : "l"(&g_barrier), "r"(1u) : "memory");
        ticket += 1;
        unsigned goal = ((ticket - 1) / SGRID + 1) * SGRID;
        unsigned cur;
        do {
            asm volatile("ld.acquire.gpu.u32 %0, [%1];"
                         : "=r"(cur) : "l"(&g_barrier) : "memory");
        } while (cur < goal);
    }
    __syncthreads();
}

// ---------------- persistent setup: zero+hist+scan+place+Wpack ----------------
__global__ __launch_bounds__(STHREADS, 1) void setup_persist(
    const int* __restrict__ ei, const int* __restrict__ batch,
    const float* __restrict__ convW, int E, int n) {
    __shared__ int sh[STHREADS];
    const int t = threadIdx.x;
    const int b = blockIdx.x;
    const int gsz = SGRID * STHREADS;
    const int gtid = b * STHREADS + t;

    // phase 0: zero accumulators + pack fp16 W fragments (m16n8k16 B layout)
    for (int i = gtid; i < n; i += gsz) g_cnt[i] = 0;
    if (gtid < GMAX) g_gcnt[gtid] = 0;
    if (gtid < LMAX * DMAX) { g_bnsum[gtid] = 0.f; g_bnsumsq[gtid] = 0.f; }
    for (int idx = gtid; idx < LMAX * 1024; idx += gsz) {
        int L = idx >> 10, i = idx & 1023;
        int ks = i >> 8;               // 0..3 (k16 step)
        int gsub = (i >> 5) & 7;       // n-group of 8
        int l = i & 31;
        int tid = l & 3, gid = l >> 2;
        const float* W = convW + L * 4096;
        int k0 = ks * 16 + 2 * tid;
        int col = gsub * 8 + gid;
        g_Wpack[(L * 1024 + i) * 2]     = packh2(W[k0 * 64 + col], W[(k0 + 1) * 64 + col]);
        g_Wpack[(L * 1024 + i) * 2 + 1] = packh2(W[(k0 + 8) * 64 + col], W[(k0 + 9) * 64 + col]);
    }
    grid_bar();

    // phase 1: histograms
    for (int e = gtid; e < E; e += gsz) atomicAdd(&g_cnt[ei[E + e]], 1);
    for (int i = gtid; i < n; i += gsz) atomicAdd(&g_gcnt[batch[i]], 1);
    grid_bar();

    // phase 2: per-chunk inclusive scans (1024-wide)
    const int nchunk = (n + STHREADS - 1) / STHREADS;
    for (int c = b; c < nchunk; c += SGRID) {
        int i = c * STHREADS + t;
        int v = (i < n) ? g_cnt[i] : 0;
        sh[t] = v;
        __syncthreads();
        for (int o = 1; o < STHREADS; o <<= 1) {
            int u = (t >= o) ? sh[t - o] : 0;
            __syncthreads();
            sh[t] += u;
            __syncthreads();
        }
        if (i < n) g_incl[i] = sh[t];
        if (t == STHREADS - 1) g_part[c] = sh[STHREADS - 1];
        __syncthreads();
    }
    grid_bar();

    // phase 3: scan partials (block 0) + graph counts (block 1)
    if (b == 0) {
        if (t < 128) {
            int v = (t < nchunk) ? g_part[t] : 0;
            sh[t] = v;
            __syncthreads();
            for (int o = 1; o < 128; o <<= 1) {
                int u = (t >= o) ? sh[t - o] : 0;
                __syncthreads();
                sh[t] += u;
                __syncthreads();
            }
            g_part[t] = sh[t] - v;
        } else {
            for (int o = 1; o < 128; o <<= 1) { __syncthreads(); __syncthreads(); }
            __syncthreads();
        }
    } else if (b == 1) {
        if (t < GMAX) {
            int v = g_gcnt[t];
            sh[t] = v;
            __syncthreads();
            for (int o = 1; o < GMAX; o <<= 1) {
                int u = (t >= o) ? sh[t - o] : 0;
                __syncthreads();
                sh[t] += u;
                __syncthreads();
            }
            g_goff[t] = sh[t] - v;
        } else {
            for (int o = 1; o < GMAX; o <<= 1) { __syncthreads(); __syncthreads(); }
            __syncthreads();
        }
    }
    grid_bar();

    // phase 4: finish CSR rowptrs + dinv
    for (int i = gtid; i < n; i += gsz) {
        int c = g_cnt[i];
        int incl = g_incl[i] + g_part[i / STHREADS];
        int rp = incl - c;
        g_rowptr[i] = rp;
        g_wpos[i]   = rp;
        g_dinv[i]   = rsqrtf((float)(c + 1));
        if (i == n - 1) g_rowptr[n] = incl;
    }
    grid_bar();

    // phase 5: place edges
    for (int e = gtid; e < E; e += gsz) {
        int s = ei[e], d = ei[E + e];
        g_srcs[atomicAdd(&g_wpos[d], 1)] = s;
    }
}

// ---------------- fused layer: [BN+res+LN+GELU transform] + fp16 HMMA GEMM ----
__global__ __launch_bounds__(256) void fused_layer(
    const float* __restrict__ xsrc,
    const __half2* __restrict__ pre2,
    const float* __restrict__ bnsum, const float* __restrict__ bnsumsq,
    const float* __restrict__ bng, const float* __restrict__ bnb,
    const float* __restrict__ lng, const float* __restrict__ lnb,
    float* __restrict__ hio, int useRes,
    const unsigned* __restrict__ Wp, float invN, int n) {
    __shared__ unsigned Bf[2048];         // fp16 B fragments (8 KB)
    __shared__ unsigned Hsw[64 * HSW];    // fp16 H tile, 36 words/row (9 KB)
    int t = threadIdx.x;
    int w = t >> 5, lane = t & 31;
    int gid = lane >> 2, tid = lane & 3;

    // coalesced copy of prepacked fragments
    for (int i = t; i < 512; i += 256)
        ((uint4*)Bf)[i] = ((const uint4*)Wp)[i];

    int row0 = blockIdx.x * 64;
    if (pre2 == nullptr) {
        for (int i = t; i < 1024; i += 256) {
            int r = i >> 4, q = i & 15;
            int row = row0 + r;
            float4 v = (row < n) ? __ldg(&((const float4*)xsrc)[row * 16 + q])
                                 : make_float4(0.f, 0.f, 0.f, 0.f);
            Hsw[r * HSW + 2 * q]     = packh2(v.x, v.y);
            Hsw[r * HSW + 2 * q + 1] = packh2(v.z, v.w);
        }
    } else {
        int f0 = 2 * lane, f1 = f0 + 1;
        float mu0 = bnsum[f0] * invN;
        float var0 = bnsumsq[f0] * invN - mu0 * mu0;
        float sc0 = rsqrtf(var0 + 1e-5f) * bng[f0];
        float sh0 = bnb[f0] - mu0 * sc0;
        float mu1 = bnsum[f1] * invN;
        float var1 = bnsumsq[f1] * invN - mu1 * mu1;
        float sc1 = rsqrtf(var1 + 1e-5f) * bng[f1];
        float sh1 = bnb[f1] - mu1 * sc1;
        float lg0 = lng[f0], lb0 = lnb[f0];
        float lg1 = lng[f1], lb1 = lnb[f1];
#pragma unroll
        for (int rr = 0; rr < 8; rr++) {
            int r = w * 8 + rr;
            int row = row0 + r;
            if (row < n) {
                float2 pv = __half22float2(pre2[row * 32 + lane]);
                float v0 = pv.x * sc0 + sh0;
                float v1 = pv.y * sc1 + sh1;
                if (useRes) {
                    float2 hv = ((const float2*)hio)[row * 32 + lane];
                    v0 += hv.x; v1 += hv.y;
                }
                float s = wsum(v0 + v1);
                float mu = s * (1.0f / 64.0f);
                float d0 = v0 - mu, d1 = v1 - mu;
                float vv = wsum(d0 * d0 + d1 * d1);
                float rstd = rsqrtf(vv * (1.0f / 64.0f) + 1e-5f);
                float y0 = gelu_exact(d0 * rstd * lg0 + lb0);
                float y1 = gelu_exact(d1 * rstd * lg1 + lb1);
                Hsw[r * HSW + lane] = packh2(y0, y1);
                float2 st; st.x = y0; st.y = y1;
                ((float2*)hio)[row * 32 + lane] = st;
            } else {
                Hsw[r * HSW + lane] = 0u;
            }
        }
    }
    __syncthreads();

    int m0 = (w & 3) * 16;
    int n0 = (w >> 2) * 32;
    float c[4][4];
#pragma unroll
    for (int s = 0; s < 4; s++)
#pragma unroll
        for (int j = 0; j < 4; j++) c[s][j] = 0.f;

    const unsigned* Ar0 = &Hsw[(m0 + gid) * HSW];
    const unsigned* Ar1 = &Hsw[(m0 + gid + 8) * HSW];
#pragma unroll
    for (int ks = 0; ks < 4; ks++) {
        int k0 = ks * 8;                 // 16 halves = 8 words per k-step
        unsigned a0 = Ar0[k0 + tid];
        unsigned a1 = Ar1[k0 + tid];
        unsigned a2 = Ar0[k0 + tid + 4];
        unsigned a3 = Ar1[k0 + tid + 4];
#pragma unroll
        for (int s = 0; s < 4; s++) {
            int gsub = (n0 >> 3) + s;
            uint2 b = ((const uint2*)Bf)[(ks * 8 + gsub) * 32 + lane];
            mma_f16(c[s][0], c[s][1], c[s][2], c[s][3],
                    a0, a1, a2, a3, b.x, b.y);
        }
    }

    int rowa = row0 + m0 + gid;
    int rowb = rowa + 8;
    float dia = (rowa < n) ? g_dinv[rowa] : 0.f;
    float dib = (rowb < n) ? g_dinv[rowb] : 0.f;
    __half2* hw = (__half2*)g_hws2;
#pragma unroll
    for (int s = 0; s < 4; s++) {
        int col = n0 + s * 8 + tid * 2;
        if (rowa < n)
            hw[rowa * 32 + (col >> 1)] = __floats2half2_rn(c[s][0] * dia, c[s][1] * dia);
        if (rowb < n)
            hw[rowb * 32 + (col >> 1)] = __floats2half2_rn(c[s][2] * dib, c[s][3] * dib);
    }
}

// ---- CSR aggregate: 4 rows/warp, 8 lanes x 16B per row, + BN partials --------
__global__ __launch_bounds__(512) void aggregate(const float* __restrict__ convB,
                                                 float* __restrict__ bnsum,
                                                 float* __restrict__ bnsumsq,
                                                 int n) {
    __shared__ float bs[64], bs2[64];
    int t = threadIdx.x;
    if (t < 64) { bs[t] = 0.f; bs2[t] = 0.f; }
    __syncthreads();
    int warp = (blockIdx.x * 512 + t) >> 5;
    int lane = t & 31;
    int sub = lane & 7;
    int group = lane >> 3;
    int r = warp * 4 + group;
    float a[8];
#pragma unroll
    for (int j = 0; j < 8; j++) a[j] = 0.f;
    float psum[8], psq[8];
    bool valid = (r < n);
    if (valid) {
        acc8(((const uint4*)g_hws2)[r * 8 + sub], a);
        int p0 = g_rowptr[r], p1 = g_rowptr[r + 1];
#pragma unroll 4
        for (int p = p0; p < p1; p++) {
            int s = g_srcs[p];
            acc8(((const uint4*)g_hws2)[s * 8 + sub], a);
        }
        float di = g_dinv[r];
#pragma unroll
        for (int j = 0; j < 8; j++) {
            float pv = fmaf(di, a[j], convB[sub * 8 + j]);
            a[j] = pv;
            psum[j] = pv;
            psq[j] = pv * pv;
        }
        __half2 h0 = __floats2half2_rn(a[0], a[1]);
        __half2 h1 = __floats2half2_rn(a[2], a[3]);
        __half2 h2 = __floats2half2_rn(a[4], a[5]);
        __half2 h3 = __floats2half2_rn(a[6], a[7]);
        uint4 st;
        st.x = *(unsigned*)&h0; st.y = *(unsigned*)&h1;
        st.z = *(unsigned*)&h2; st.w = *(unsigned*)&h3;
        ((uint4*)g_pre2)[r * 8 + sub] = st;
    } else {
#pragma unroll
        for (int j = 0; j < 8; j++) { psum[j] = 0.f; psq[j] = 0.f; }
    }
#pragma unroll
    for (int j = 0; j < 8; j++) {
        psum[j] += __shfl_xor_sync(0xffffffffu, psum[j], 8);
        psq[j]  += __shfl_xor_sync(0xffffffffu, psq[j], 8);
        psum[j] += __shfl_xor_sync(0xffffffffu, psum[j], 16);
        psq[j]  += __shfl_xor_sync(0xffffffffu, psq[j], 16);
    }
    if (group == 0) {
#pragma unroll
        for (int j = 0; j < 8; j++) {
            atomicAdd(&bs[sub * 8 + j], psum[j]);
            atomicAdd(&bs2[sub * 8 + j], psq[j]);
        }
    }
    __syncthreads();
    if (t < 64) {
        atomicAdd(&bnsum[t], bs[t]);
        atomicAdd(&bnsumsq[t], bs2[t]);
    }
}

// ---- fused: final BN+res+LN+GELU transform + pool + MLP head per graph -------
__global__ __launch_bounds__(256) void pool_mlp(
    const float* __restrict__ bnsum, const float* __restrict__ bnsumsq,
    const float* __restrict__ bng, const float* __restrict__ bnb,
    const float* __restrict__ lng, const float* __restrict__ lnb,
    const float* __restrict__ W1, const float* __restrict__ b1,
    const float* __restrict__ l1g, const float* __restrict__ l1b,
    const float* __restrict__ W2, const float* __restrict__ b2,
    const float* __restrict__ l2g, const float* __restrict__ l2b,
    const float* __restrict__ W3, const float* __restrict__ b3,
    float* __restrict__ out, float invN) {
    int g = blockIdx.x, t = threadIdx.x;
    __shared__ float zs[192];
    __shared__ float shs[8][64], shm[8][64];
    __shared__ float s2[128];
    __shared__ float red[128];

    int start = g_goff[g], cnt = g_gcnt[g];
    int w = t >> 5, lane = t & 31;
    int f0 = 2 * lane, f1 = f0 + 1;

    float mu0 = bnsum[f0] * invN;
    float var0 = bnsumsq[f0] * invN - mu0 * mu0;
    float sc0 = rsqrtf(var0 + 1e-5f) * bng[f0];
    float sh0 = bnb[f0] - mu0 * sc0;
    float mu1 = bnsum[f1] * invN;
    float var1 = bnsumsq[f1] * invN - mu1 * mu1;
    float sc1 = rsqrtf(var1 + 1e-5f) * bng[f1];
    float sh1 = bnb[f1] - mu1 * sc1;
    float lg0 = lng[f0], lb0 = lnb[f0];
    float lg1 = lng[f1], lb1 = lnb[f1];

    float s0 = 0.f, s1 = 0.f, m0 = -FLT_MAX, m1 = -FLT_MAX;
    for (int r = start + w; r < start + cnt; r += 8) {
        float2 pv = __half22float2(g_pre2[r * 32 + lane]);
        float2 hv = ((const float2*)g_h)[r * 32 + lane];
        float v0 = pv.x * sc0 + sh0 + hv.x;
        float v1 = pv.y * sc1 + sh1 + hv.y;
        float s = wsum(v0 + v1);
        float mu = s * (1.0f / 64.0f);
        float d0 = v0 - mu, d1 = v1 - mu;
        float vv = wsum(d0 * d0 + d1 * d1);
        float rstd = rsqrtf(vv * (1.0f / 64.0f) + 1e-5f);
        float y0 = gelu_exact(d0 * rstd * lg0 + lb0);
        float y1 = gelu_exact(d1 * rstd * lg1 + lb1);
        s0 += y0; s1 += y1;
        m0 = fmaxf(m0, y0); m1 = fmaxf(m1, y1);
    }
    shs[w][f0] = s0; shs[w][f1] = s1;
    shm[w][f0] = m0; shm[w][f1] = m1;
    __syncthreads();
    if (t < 64) {
        float s = 0.f, m = -FLT_MAX;
#pragma unroll
        for (int k = 0; k < 8; k++) {
            s += shs[k][t];
            m = fmaxf(m, shm[k][t]);
        }
        float mean = (cnt > 0) ? s / (float)cnt : 0.f;
        if (cnt == 0) { m = 0.f; s = 0.f; }
        zs[t] = mean;
        zs[64 + t] = m;
        zs[128 + t] = s;
    }
    __syncthreads();

    float accv = 0.f;
    if (t < 128) {
        accv = b1[t];
#pragma unroll 4
        for (int k = 0; k < 192; k++) accv = fmaf(zs[k], W1[k * 128 + t], accv);
        red[t] = accv;
    }
    __syncthreads();
    if (t < 128) {
        for (int o = 64; o > 0; o >>= 1) {
            if (t < o) red[t] += red[t + o];
            __syncwarp(0xffffffffu);
            if (o > 32) __syncthreads();
        }
    }
    __syncthreads();
    float mu = red[0] * (1.0f / 128.0f);
    __syncthreads();
    float dv = accv - mu;
    if (t < 128) red[t] = dv * dv;
    __syncthreads();
    if (t < 128) {
        for (int o = 64; o > 0; o >>= 1) {
            if (t < o) red[t] += red[t + o];
            __syncwarp(0xffffffffu);
            if (o > 32) __syncthreads();
        }
    }
    __syncthreads();
    float rstd = rsqrtf(red[0] * (1.0f / 128.0f) + 1e-5f);
    __syncthreads();
    if (t < 128) s2[t] = gelu_exact(dv * rstd * l1g[t] + l1b[t]);
    __syncthreads();
    float acc2 = 0.f;
    if (t < 64) {
        acc2 = b2[t];
#pragma unroll 4
        for (int k = 0; k < 128; k++) acc2 = fmaf(s2[k], W2[k * 64 + t], acc2);
    }
    if (t < 128) red[t] = (t < 64) ? acc2 : 0.f;
    __syncthreads();
    if (t < 128) {
        for (int o = 64; o > 0; o >>= 1) {
            if (t < o) red[t] += red[t + o];
            __syncwarp(0xffffffffu);
            if (o > 32) __syncthreads();
        }
    }
    __syncthreads();
    float mu2 = red[0] * (1.0f / 64.0f);
    __syncthreads();
    float dv2 = acc2 - mu2;
    if (t < 128) red[t] = (t < 64) ? dv2 * dv2 : 0.f;
    __syncthreads();
    if (t < 128) {
        for (int o = 64; o > 0; o >>= 1) {
            if (t < o) red[t] += red[t + o];
            __syncwarp(0xffffffffu);
            if (o > 32) __syncthreads();
        }
    }
    __syncthreads();
    float rstd2 = rsqrtf(red[0] * (1.0f / 64.0f) + 1e-5f);
    __syncthreads();
    float y2 = 0.f;
    if (t < 64) y2 = gelu_exact(dv2 * rstd2 * l2g[t] + l2b[t]);
    if (t < 128) red[t] = (t < 64) ? y2 * W3[t] : 0.f;
    __syncthreads();
    if (t < 128) {
        for (int o = 64; o > 0; o >>= 1) {
            if (t < o) red[t] += red[t + o];
            __syncwarp(0xffffffffu);
            if (o > 32) __syncthreads();
        }
    }
    __syncthreads();
    if (t == 0) out[g] = red[0] + b3[0];
}

// ---------------- host ----------------
extern "C" void kernel_launch(void* const* d_in, const int* in_sizes, int n_in,
                              void* d_out, int out_size) {
    const float* x     = (const float*)d_in[0];
    const int*   ei    = (const int*)d_in[1];
    const int*   batch = (const int*)d_in[2];
    const float* convW = (const float*)d_in[3];
    const float* convB = (const float*)d_in[4];
    const float* bn_g  = (const float*)d_in[5];
    const float* bn_b  = (const float*)d_in[6];
    const float* ln_g  = (const float*)d_in[7];
    const float* ln_b  = (const float*)d_in[8];
    const float* W1    = (const float*)d_in[9];
    const float* b1    = (const float*)d_in[10];
    const float* l1g   = (const float*)d_in[11];
    const float* l1b   = (const float*)d_in[12];
    const float* W2    = (const float*)d_in[13];
    const float* b2    = (const float*)d_in[14];
    const float* l2g   = (const float*)d_in[15];
    const float* l2b   = (const float*)d_in[16];
    const float* W3    = (const float*)d_in[17];
    const float* b3    = (const float*)d_in[18];
    float* out = (float*)d_out;

    const int N = in_sizes[0] / 64;
    const int E = in_sizes[1] / 2;
    const int G = out_size;
    const float invN = 1.0f / (float)N;

    float* p_h; __half2* p_pre2; float* p_bnsum; float* p_bnsumsq; unsigned* p_wp;
    cudaGetSymbolAddress((void**)&p_h,       g_h);
    cudaGetSymbolAddress((void**)&p_pre2,    g_pre2);
    cudaGetSymbolAddress((void**)&p_bnsum,   g_bnsum);
    cudaGetSymbolAddress((void**)&p_bnsumsq, g_bnsumsq);
    cudaGetSymbolAddress((void**)&p_wp,      g_Wpack);

    setup_persist<<<SGRID, STHREADS>>>(ei, batch, convW, E, N);

    int fgrid = (N + 63) / 64;
    int agrid = (N + 63) / 64;

    fused_layer<<<fgrid, 256>>>(x, nullptr, nullptr, nullptr, nullptr,
                                nullptr, nullptr, nullptr, p_h, 0,
                                p_wp, invN, N);
    aggregate<<<agrid, 512>>>(convB, p_bnsum, p_bnsumsq, N);

    fused_layer<<<fgrid, 256>>>(nullptr, p_pre2, p_bnsum, p_bnsumsq,
                                bn_g, bn_b, ln_g, ln_b,
                                p_h, 0, p_wp + 2048, invN, N);
    aggregate<<<agrid, 512>>>(convB + 64, p_bnsum + 64, p_bnsumsq + 64, N);

    fused_layer<<<fgrid, 256>>>(nullptr, p_pre2, p_bnsum + 64, p_bnsumsq + 64,
                                bn_g + 64, bn_b + 64, ln_g + 64, ln_b + 64,
                                p_h, 1, p_wp + 2 * 2048, invN, N);
    aggregate<<<agrid, 512>>>(convB + 2 * 64, p_bnsum + 2 * 64, p_bnsumsq + 2 * 64, N);

    pool_mlp<<<G, 256>>>(p_bnsum + 2 * 64, p_bnsumsq + 2 * 64,
                         bn_g + 2 * 64, bn_b + 2 * 64,
                         ln_g + 2 * 64, ln_b + 2 * 64,
                         W1, b1, l1g, l1b, W2, b2, l2g, l2b, W3, b3, out, invN);
}